// round 4
// baseline (speedup 1.0000x reference)
#include <cuda_runtime.h>
#include <cstdint>
#include <cstdio>

#define BATCH 8
#define NPTS 8192
#define N1 8193
#define SPTS 1024
#define FEATC 64
#define CIN0 67
#define NS0 32
#define NS1 64
#define M0 (BATCH*SPTS*NS0)   /* 262144 */
#define M1 (BATCH*SPTS*NS1)   /* 524288 */

// ---------------- static scratch (allocation is forbidden) ----------------
__device__ float  d_bufA[(size_t)256*M1];   // 537 MB  (Y1 / Y3)
__device__ float  d_bufB[(size_t)128*M1];   // 268 MB  (Y2)
__device__ float  d_bufC[(size_t)CIN0*M1];  // 140 MB  (gathered X0)
__device__ float  d_featT[(size_t)BATCH*NPTS*FEATC]; // 16.8 MB
__device__ float  d_meanv[BATCH*3];
__device__ int    d_idx0[(size_t)BATCH*SPTS*NS0];
__device__ int    d_idx1[(size_t)BATCH*SPTS*NS1];
__device__ double d_gsum[6*256];
__device__ double d_gsq [6*256];
__device__ float  d_scl [6*256];
__device__ float  d_shf [6*256];

// ---------------- helpers: packed f32x2 FMA ----------------
typedef unsigned long long u64;
__device__ __forceinline__ u64 pk2(float x, float y){
    u64 r; asm("mov.b64 %0, {%1,%2};" : "=l"(r) : "f"(x), "f"(y)); return r;
}
__device__ __forceinline__ float2 up2(u64 v){
    float2 r; asm("mov.b64 {%0,%1}, %2;" : "=f"(r.x), "=f"(r.y) : "l"(v)); return r;
}
__device__ __forceinline__ void fma2(u64& d, u64 a, u64 b){
    asm("fma.rn.f32x2 %0, %1, %2, %0;" : "+l"(d) : "l"(a), "l"(b));
}

// ---------------- zero stats ----------------
__global__ void zero_stats_kernel(double* gsum, double* gsq){
    int i = blockIdx.x*blockDim.x + threadIdx.x;
    if(i < 6*256){ gsum[i]=0.0; gsq[i]=0.0; }
}

// ---------------- mean over points ----------------
__global__ void mean_kernel(const float* __restrict__ xyz, float* __restrict__ meanv){
    int b = blockIdx.x, t = threadIdx.x;
    double sx=0, sy=0, sz=0;
    for(int n=t; n<NPTS; n+=256){
        const float* p = xyz + ((size_t)b*NPTS + n)*3;
        sx += (double)p[0]; sy += (double)p[1]; sz += (double)p[2];
    }
    __shared__ double rx[256], ry[256], rz[256];
    rx[t]=sx; ry[t]=sy; rz[t]=sz; __syncthreads();
    for(int o=128;o;o>>=1){
        if(t<o){ rx[t]+=rx[t+o]; ry[t]+=ry[t+o]; rz[t]+=rz[t+o]; }
        __syncthreads();
    }
    if(t==0){
        meanv[b*3+0]=(float)(rx[0]/NPTS);
        meanv[b*3+1]=(float)(ry[0]/NPTS);
        meanv[b*3+2]=(float)(rz[0]/NPTS);
    }
}

// ---------------- farthest point sampling ----------------
// pts[0] = mean, pts[1..8192] = xyz. Exact reference arithmetic: no FMA
// contraction, sum order ((dx2+dy2)+dz2), first-occurrence argmax.
__global__ __launch_bounds__(1024) void fps_kernel(const float* __restrict__ xyz,
                                                   const float* __restrict__ meanv,
                                                   float* __restrict__ newxyz){
    int b = blockIdx.x, t = threadIdx.x;
    __shared__ float c[3];
    __shared__ float sv[32]; __shared__ int si[32];
    __shared__ int sfar;
    float px[9], py[9], pz[9], dist[9];
    #pragma unroll
    for(int j=0;j<9;j++){
        int i = t + j*1024;
        if(i < N1){
            if(i==0){ px[j]=meanv[b*3]; py[j]=meanv[b*3+1]; pz[j]=meanv[b*3+2]; }
            else{
                const float* p = xyz + ((size_t)b*NPTS + (i-1))*3;
                px[j]=p[0]; py[j]=p[1]; pz[j]=p[2];
            }
            dist[j] = 1e10f;
        } else { px[j]=py[j]=pz[j]=0.f; dist[j] = -1.0f; }
    }
    if(t==0){ c[0]=meanv[b*3]; c[1]=meanv[b*3+1]; c[2]=meanv[b*3+2]; }
    __syncthreads();

    for(int s=0;s<SPTS;s++){
        float cx=c[0], cy=c[1], cz=c[2];
        if(t==0){
            float* o = newxyz + ((size_t)b*SPTS + s)*3;
            o[0]=cx; o[1]=cy; o[2]=cz;
        }
        float bv = -2.0f; int bi = 0;
        #pragma unroll
        for(int j=0;j<9;j++){
            int i = t + j*1024;
            if(i < N1){
                float dx = __fadd_rn(px[j], -cx);
                float dy = __fadd_rn(py[j], -cy);
                float dz = __fadd_rn(pz[j], -cz);
                float d  = __fadd_rn(__fadd_rn(__fmul_rn(dx,dx), __fmul_rn(dy,dy)), __fmul_rn(dz,dz));
                float nd = fminf(dist[j], d);
                dist[j] = nd;
                if(nd > bv){ bv = nd; bi = i; }
            }
        }
        // warp reduce: max value, min index on ties
        #pragma unroll
        for(int o=16;o;o>>=1){
            float ov = __shfl_down_sync(0xffffffffu, bv, o);
            int   oi = __shfl_down_sync(0xffffffffu, bi, o);
            if(ov > bv || (ov == bv && oi < bi)){ bv = ov; bi = oi; }
        }
        if((t & 31) == 0){ sv[t>>5] = bv; si[t>>5] = bi; }
        __syncthreads();
        if(t < 32){
            bv = sv[t]; bi = si[t];
            #pragma unroll
            for(int o=16;o;o>>=1){
                float ov = __shfl_down_sync(0xffffffffu, bv, o);
                int   oi = __shfl_down_sync(0xffffffffu, bi, o);
                if(ov > bv || (ov == bv && oi < bi)){ bv = ov; bi = oi; }
            }
            if(t==0) sfar = bi;
        }
        __syncthreads();
        int far = sfar;
        int jj = far >> 10, ii = far & 1023;
        if(t == ii){ c[0]=px[jj]; c[1]=py[jj]; c[2]=pz[jj]; }
        __syncthreads();
    }
}

// ---------------- feature transpose (B,C,N) -> (B,N,C) ----------------
__global__ void transpose_kernel(const float* __restrict__ f, float* __restrict__ ft){
    __shared__ float tile[32][33];
    int b = blockIdx.z;
    int n0 = blockIdx.x*32, c0 = blockIdx.y*32;
    int tx = threadIdx.x, ty = threadIdx.y;
    #pragma unroll
    for(int i=0;i<32;i+=8)
        tile[ty+i][tx] = f[((size_t)b*FEATC + (c0+ty+i))*NPTS + n0 + tx];
    __syncthreads();
    #pragma unroll
    for(int i=0;i<32;i+=8)
        ft[((size_t)b*NPTS + (n0+ty+i))*FEATC + c0 + tx] = tile[tx][ty+i];
}

// ---------------- ball query (both radii in one pass) ----------------
__global__ __launch_bounds__(256) void ballq_kernel(const float* __restrict__ xyz,
                                                    const float* __restrict__ nx,
                                                    int* __restrict__ idx0,
                                                    int* __restrict__ idx1){
    int gw = (blockIdx.x*blockDim.x + threadIdx.x) >> 5;
    int lane = threadIdx.x & 31;
    int b = gw >> 10, s = gw & 1023;
    const float R20 = (float)(0.4*0.4);
    const float R21 = (float)(0.8*0.8);
    const float* cp = nx + ((size_t)b*SPTS + s)*3;
    float cx=cp[0], cy=cp[1], cz=cp[2];
    int cnt0=0, cnt1=0, first0=0, first1=0;
    size_t base0 = ((size_t)b*SPTS + s)*NS0;
    size_t base1 = ((size_t)b*SPTS + s)*NS1;
    unsigned lmask = (1u << lane) - 1u;
    for(int ch=0; ch<NPTS/32; ch++){
        if(cnt0 >= NS0 && cnt1 >= NS1) break;
        int n = ch*32 + lane;
        const float* p = xyz + ((size_t)b*NPTS + n)*3;
        float dx = __fadd_rn(cx, -p[0]);
        float dy = __fadd_rn(cy, -p[1]);
        float dz = __fadd_rn(cz, -p[2]);
        float d2 = __fadd_rn(__fadd_rn(__fmul_rn(dx,dx), __fmul_rn(dy,dy)), __fmul_rn(dz,dz));
        unsigned m1 = __ballot_sync(0xffffffffu, d2 < R21);
        unsigned m0 = __ballot_sync(0xffffffffu, d2 < R20);
        if(m0 && cnt0 < NS0){
            if(cnt0 == 0) first0 = ch*32 + __ffs(m0) - 1;
            if((m0 >> lane) & 1){
                int r = __popc(m0 & lmask);
                if(cnt0 + r < NS0) idx0[base0 + cnt0 + r] = n;
            }
            cnt0 = min(NS0, cnt0 + __popc(m0));
        }
        if(m1 && cnt1 < NS1){
            if(cnt1 == 0) first1 = ch*32 + __ffs(m1) - 1;
            if((m1 >> lane) & 1){
                int r = __popc(m1 & lmask);
                if(cnt1 + r < NS1) idx1[base1 + cnt1 + r] = n;
            }
            cnt1 = min(NS1, cnt1 + __popc(m1));
        }
    }
    int p0 = (cnt0 > 0) ? first0 : 0;
    for(int k=cnt0+lane; k<NS0; k+=32) idx0[base0+k] = p0;
    int p1 = (cnt1 > 0) ? first1 : 0;
    for(int k=cnt1+lane; k<NS1; k+=32) idx1[base1+k] = p1;
}

// ---------------- gather: build X0 [67][M] ----------------
__global__ void gather_kernel(const float* __restrict__ xyz, const float* __restrict__ ft,
                              const float* __restrict__ nx, const int* __restrict__ idx,
                              float* __restrict__ X, int ns, int M){
    int m = blockIdx.x*blockDim.x + threadIdx.x;
    if(m >= M) return;
    int sc = m / ns;
    int s = sc & 1023, b = sc >> 10;
    int id = idx[m];
    const float* p = xyz + ((size_t)b*NPTS + id)*3;
    const float* c = nx + ((size_t)b*SPTS + s)*3;
    X[(size_t)0*M + m] = p[0]-c[0];
    X[(size_t)1*M + m] = p[1]-c[1];
    X[(size_t)2*M + m] = p[2]-c[2];
    const float4* fr = (const float4*)(ft + ((size_t)b*NPTS + id)*FEATC);
    #pragma unroll
    for(int c4=0;c4<16;c4++){
        float4 v = fr[c4];
        size_t r = (size_t)(3 + c4*4)*M + m;
        X[r] = v.x; X[r+(size_t)M] = v.y; X[r+2*(size_t)M] = v.z; X[r+3*(size_t)M] = v.w;
    }
}

// ---------------- GEMM: Y[Cout][M] = W[Cout][Cin] * transform(X[Cin][M]) ----------------
// transform(x) = relu(tsc[c]*x + tsh[c]) if tsc != null else x.
// Accumulates per-out-channel sum / sumsq into gsum / gsq (double atomics).
__global__ __launch_bounds__(256) void gemm_kernel(const float* __restrict__ W,
        const float* __restrict__ X, float* __restrict__ Y,
        int Cin, int Cout, int M,
        const float* __restrict__ tsc, const float* __restrict__ tsh,
        double* __restrict__ gsum, double* __restrict__ gsq){
    __shared__ float Wall[128*64];  // [k][o]
    __shared__ float Xs[16*128];    // [k][m]
    int tid = threadIdx.x;
    int ty = tid >> 4, tx = tid & 15;
    int m0 = blockIdx.x * 128;
    int ob = blockIdx.y * 64;
    for(int i=tid; i<128*64; i+=256){
        int k = i >> 6, o = i & 63;
        Wall[i] = (k < Cin) ? W[(size_t)(ob + o)*Cin + k] : 0.0f;
    }
    u64 acc[4][4];
    #pragma unroll
    for(int r=0;r<4;r++)
        #pragma unroll
        for(int c=0;c<4;c++) acc[r][c] = 0ull;
    int kch = (Cin + 15) >> 4;
    for(int kc=0; kc<kch; kc++){
        int rr = tid >> 4, cc = (tid & 15)*8;
        int cin = kc*16 + rr;
        float4 a = make_float4(0.f,0.f,0.f,0.f), bv = a;
        if(cin < Cin){
            const float4* p = (const float4*)(X + (size_t)cin*M + m0 + cc);
            a = p[0]; bv = p[1];
            if(tsc){
                float s_ = tsc[cin], h_ = tsh[cin];
                a.x = fmaxf(0.f, fmaf(s_, a.x, h_));
                a.y = fmaxf(0.f, fmaf(s_, a.y, h_));
                a.z = fmaxf(0.f, fmaf(s_, a.z, h_));
                a.w = fmaxf(0.f, fmaf(s_, a.w, h_));
                bv.x = fmaxf(0.f, fmaf(s_, bv.x, h_));
                bv.y = fmaxf(0.f, fmaf(s_, bv.y, h_));
                bv.z = fmaxf(0.f, fmaf(s_, bv.z, h_));
                bv.w = fmaxf(0.f, fmaf(s_, bv.w, h_));
            }
        }
        *(float4*)&Xs[rr*128 + cc]     = a;
        *(float4*)&Xs[rr*128 + cc + 4] = bv;
        __syncthreads();
        #pragma unroll
        for(int kk=0; kk<16; kk++){
            float4 w = *(const float4*)&Wall[(kc*16 + kk)*64 + ty*4];
            const ulonglong2* xp = (const ulonglong2*)&Xs[kk*128 + tx*8];
            ulonglong2 xa = xp[0], xb = xp[1];
            u64 w0 = pk2(w.x, w.x), w1 = pk2(w.y, w.y);
            u64 w2 = pk2(w.z, w.z), w3 = pk2(w.w, w.w);
            fma2(acc[0][0], w0, xa.x); fma2(acc[0][1], w0, xa.y);
            fma2(acc[0][2], w0, xb.x); fma2(acc[0][3], w0, xb.y);
            fma2(acc[1][0], w1, xa.x); fma2(acc[1][1], w1, xa.y);
            fma2(acc[1][2], w1, xb.x); fma2(acc[1][3], w1, xb.y);
            fma2(acc[2][0], w2, xa.x); fma2(acc[2][1], w2, xa.y);
            fma2(acc[2][2], w2, xb.x); fma2(acc[2][3], w2, xb.y);
            fma2(acc[3][0], w3, xa.x); fma2(acc[3][1], w3, xa.y);
            fma2(acc[3][2], w3, xb.x); fma2(acc[3][3], w3, xb.y);
        }
        __syncthreads();
    }
    // epilogue: stats + store
    #pragma unroll
    for(int r=0;r<4;r++){
        float y[8];
        #pragma unroll
        for(int c=0;c<4;c++){ float2 f = up2(acc[r][c]); y[2*c]=f.x; y[2*c+1]=f.y; }
        float s=0.f, q=0.f;
        #pragma unroll
        for(int c=0;c<8;c++){ s += y[c]; q += y[c]*y[c]; }
        #pragma unroll
        for(int o=8;o;o>>=1){
            s += __shfl_xor_sync(0xffffffffu, s, o);
            q += __shfl_xor_sync(0xffffffffu, q, o);
        }
        int orow = ob + ty*4 + r;
        if(tx == 0){
            atomicAdd(&gsum[orow], (double)s);
            atomicAdd(&gsq[orow],  (double)q);
        }
        float4* yp = (float4*)(Y + (size_t)orow*M + m0 + tx*8);
        yp[0] = make_float4(y[0], y[1], y[2], y[3]);
        yp[1] = make_float4(y[4], y[5], y[6], y[7]);
    }
}

// ---------------- finalize BN params ----------------
__global__ void finalize_kernel(const double* __restrict__ gsum, const double* __restrict__ gsq,
                                const float* __restrict__ g, const float* __restrict__ bb,
                                float* __restrict__ sc, float* __restrict__ sh,
                                int Cout, double invM){
    int o = blockIdx.x*blockDim.x + threadIdx.x;
    if(o < Cout){
        double mean = gsum[o]*invM;
        double var  = gsq[o]*invM - mean*mean;
        float s = (float)((double)g[o] / sqrt(var + 1e-5));
        sc[o] = s;
        sh[o] = fmaf(-(float)mean, s, bb[o]);
    }
}

// ---------------- BN + ReLU + maxpool over nsample ----------------
__global__ void maxpool_kernel(const float* __restrict__ Y, const float* __restrict__ sc,
                               const float* __restrict__ sh, float* __restrict__ out,
                               int Cout, int ns, int M, int coff){
    int tid = blockIdx.x*blockDim.x + threadIdx.x;
    int total = BATCH*Cout*SPTS;
    if(tid >= total) return;
    int s = tid & 1023;
    int co = (tid >> 10) % Cout;
    int b = tid / (Cout*SPTS);
    float s_ = sc[co], h_ = sh[co];
    const float4* p = (const float4*)(Y + (size_t)co*M + (size_t)(b*SPTS + s)*ns);
    float mx = 0.0f; // relu >= 0 and ns >= 1, so 0 init == max over relu values
    for(int k=0; k<ns/4; k++){
        float4 v = p[k];
        mx = fmaxf(mx, fmaf(s_, v.x, h_));
        mx = fmaxf(mx, fmaf(s_, v.y, h_));
        mx = fmaxf(mx, fmaf(s_, v.z, h_));
        mx = fmaxf(mx, fmaf(s_, v.w, h_));
    }
    out[((size_t)(b*384 + coff + co))*SPTS + s] = mx;
}

// ---------------- launch ----------------
extern "C" void kernel_launch(void* const* d_in, const int* in_sizes, int n_in,
                              void* d_out, int out_size){
    const float* xyz  = (const float*)d_in[0];
    const float* feat = (const float*)d_in[1];
    const float *w[6], *g[6], *bb[6];
    for(int L=0; L<6; L++){
        w[L]  = (const float*)d_in[2 + L*3];
        g[L]  = (const float*)d_in[3 + L*3];
        bb[L] = (const float*)d_in[4 + L*3];
    }
    float* out = (float*)d_out;
    float* newxyz  = out;                    // (8,1024,3)
    float* outfeat = out + (size_t)BATCH*SPTS*3;  // (8,384,1024)

    void *pA,*pB,*pC,*pFT,*pM,*pI0,*pI1,*pSum,*pSq,*pSc,*pSh;
    cudaGetSymbolAddress(&pA,  d_bufA);
    cudaGetSymbolAddress(&pB,  d_bufB);
    cudaGetSymbolAddress(&pC,  d_bufC);
    cudaGetSymbolAddress(&pFT, d_featT);
    cudaGetSymbolAddress(&pM,  d_meanv);
    cudaGetSymbolAddress(&pI0, d_idx0);
    cudaGetSymbolAddress(&pI1, d_idx1);
    cudaGetSymbolAddress(&pSum,d_gsum);
    cudaGetSymbolAddress(&pSq, d_gsq);
    cudaGetSymbolAddress(&pSc, d_scl);
    cudaGetSymbolAddress(&pSh, d_shf);
    float* A  = (float*)pA;  float* Bf = (float*)pB;  float* C = (float*)pC;
    float* ft = (float*)pFT; float* mv = (float*)pM;
    int* i0 = (int*)pI0; int* i1 = (int*)pI1;
    double* gsum = (double*)pSum; double* gsq = (double*)pSq;
    float* scv = (float*)pSc; float* shv = (float*)pSh;

    zero_stats_kernel<<<6,256>>>(gsum, gsq);
    mean_kernel<<<BATCH,256>>>(xyz, mv);
    fps_kernel<<<BATCH,1024>>>(xyz, mv, newxyz);
    transpose_kernel<<<dim3(NPTS/32, FEATC/32, BATCH), dim3(32,8)>>>(feat, ft);
    ballq_kernel<<<(BATCH*SPTS)/8, 256>>>(xyz, newxyz, i0, i1);

    // ---- branch 0 (r=0.4, ns=32): 67 -> 64 -> 64 -> 128 ----
    gather_kernel<<<M0/256,256>>>(xyz, ft, newxyz, i0, C, NS0, M0);
    gemm_kernel<<<dim3(M0/128,1),256>>>(w[0], C,  A,  CIN0, 64,  M0, nullptr, nullptr, gsum+0*256, gsq+0*256);
    finalize_kernel<<<1,256>>>(gsum+0*256, gsq+0*256, g[0], bb[0], scv+0*256, shv+0*256, 64, 1.0/M0);
    gemm_kernel<<<dim3(M0/128,1),256>>>(w[1], A,  Bf, 64,   64,  M0, scv+0*256, shv+0*256, gsum+1*256, gsq+1*256);
    finalize_kernel<<<1,256>>>(gsum+1*256, gsq+1*256, g[1], bb[1], scv+1*256, shv+1*256, 64, 1.0/M0);
    gemm_kernel<<<dim3(M0/128,2),256>>>(w[2], Bf, A,  64,   128, M0, scv+1*256, shv+1*256, gsum+2*256, gsq+2*256);
    finalize_kernel<<<1,256>>>(gsum+2*256, gsq+2*256, g[2], bb[2], scv+2*256, shv+2*256, 128, 1.0/M0);
    maxpool_kernel<<<(BATCH*128*SPTS)/256,256>>>(A, scv+2*256, shv+2*256, outfeat, 128, NS0, M0, 0);

    // ---- branch 1 (r=0.8, ns=64): 67 -> 64 -> 128 -> 256 ----
    gather_kernel<<<M1/256,256>>>(xyz, ft, newxyz, i1, C, NS1, M1);
    gemm_kernel<<<dim3(M1/128,1),256>>>(w[3], C,  A,  CIN0, 64,  M1, nullptr, nullptr, gsum+3*256, gsq+3*256);
    finalize_kernel<<<1,256>>>(gsum+3*256, gsq+3*256, g[3], bb[3], scv+3*256, shv+3*256, 64, 1.0/M1);
    gemm_kernel<<<dim3(M1/128,2),256>>>(w[4], A,  Bf, 64,   128, M1, scv+3*256, shv+3*256, gsum+4*256, gsq+4*256);
    finalize_kernel<<<1,256>>>(gsum+4*256, gsq+4*256, g[4], bb[4], scv+4*256, shv+4*256, 128, 1.0/M1);
    gemm_kernel<<<dim3(M1/128,4),256>>>(w[5], Bf, A,  128,  256, M1, scv+4*256, shv+4*256, gsum+5*256, gsq+5*256);
    finalize_kernel<<<1,256>>>(gsum+5*256, gsq+5*256, g[5], bb[5], scv+5*256, shv+5*256, 256, 1.0/M1);
    maxpool_kernel<<<(BATCH*256*SPTS)/256,256>>>(A, scv+5*256, shv+5*256, outfeat, 256, NS1, M1, 128);
}

// round 5
// speedup vs baseline: 1.4849x; 1.4849x over previous
#include <cuda_runtime.h>
#include <cstdint>
#include <cstdio>

#define BATCH 8
#define NPTS 8192
#define N1 8193
#define SPTS 1024
#define FEATC 64
#define CIN0 67
#define NS0 32
#define NS1 64
#define M0 (BATCH*SPTS*NS0)   /* 262144 */
#define M1 (BATCH*SPTS*NS1)   /* 524288 */

// ---------------- static scratch (allocation is forbidden) ----------------
__device__ float  d_bufA[(size_t)256*M1];   // 537 MB  (Y1 / Y3)
__device__ float  d_bufB[(size_t)128*M1];   // 268 MB  (Y2)
__device__ float  d_bufC[(size_t)CIN0*M1];  // 140 MB  (gathered X0)
__device__ float  d_featT[(size_t)BATCH*NPTS*FEATC]; // 16.8 MB
__device__ float  d_meanv[BATCH*3];
__device__ int    d_idx0[(size_t)BATCH*SPTS*NS0];
__device__ int    d_idx1[(size_t)BATCH*SPTS*NS1];
__device__ double d_gsum[6*256];
__device__ double d_gsq [6*256];
__device__ float  d_scl [6*256];
__device__ float  d_shf [6*256];

// ---------------- helpers: packed f32x2 FMA ----------------
typedef unsigned long long u64;
__device__ __forceinline__ u64 pk2(float x, float y){
    u64 r; asm("mov.b64 %0, {%1,%2};" : "=l"(r) : "f"(x), "f"(y)); return r;
}
__device__ __forceinline__ float2 up2(u64 v){
    float2 r; asm("mov.b64 {%0,%1}, %2;" : "=f"(r.x), "=f"(r.y) : "l"(v)); return r;
}
__device__ __forceinline__ void fma2(u64& d, u64 a, u64 b){
    asm("fma.rn.f32x2 %0, %1, %2, %0;" : "+l"(d) : "l"(a), "l"(b));
}

// ---------------- zero stats ----------------
__global__ void zero_stats_kernel(double* gsum, double* gsq){
    int i = blockIdx.x*blockDim.x + threadIdx.x;
    if(i < 6*256){ gsum[i]=0.0; gsq[i]=0.0; }
}

// ---------------- mean over points ----------------
__global__ void mean_kernel(const float* __restrict__ xyz, float* __restrict__ meanv){
    int b = blockIdx.x, t = threadIdx.x;
    double sx=0, sy=0, sz=0;
    for(int n=t; n<NPTS; n+=256){
        const float* p = xyz + ((size_t)b*NPTS + n)*3;
        sx += (double)p[0]; sy += (double)p[1]; sz += (double)p[2];
    }
    __shared__ double rx[256], ry[256], rz[256];
    rx[t]=sx; ry[t]=sy; rz[t]=sz; __syncthreads();
    for(int o=128;o;o>>=1){
        if(t<o){ rx[t]+=rx[t+o]; ry[t]+=ry[t+o]; rz[t]+=rz[t+o]; }
        __syncthreads();
    }
    if(t==0){
        meanv[b*3+0]=(float)(rx[0]/NPTS);
        meanv[b*3+1]=(float)(ry[0]/NPTS);
        meanv[b*3+2]=(float)(rz[0]/NPTS);
    }
}

// ---------------- farthest point sampling ----------------
// Points live in REGISTERS for the distance loop (compile-time indexing only
// -> no local-memory demotion) and in SHARED for the centroid fetch.
// Exact reference arithmetic: no FMA contraction, sum order ((dx2+dy2)+dz2),
// first-occurrence argmax (min index on ties).
__global__ __launch_bounds__(1024) void fps_kernel(const float* __restrict__ xyz,
                                                   const float* __restrict__ meanv,
                                                   float* __restrict__ newxyz){
    extern __shared__ float sh[];          // sx[N1], sy[N1], sz[N1]
    float* sx = sh;
    float* sy = sh + N1;
    float* sz = sh + 2*N1;
    __shared__ float c[3];
    __shared__ float sv[32]; __shared__ int si[32];
    int b = blockIdx.x, t = threadIdx.x;

    // populate shared copy of points (pts[0] = mean, pts[1..] = xyz)
    for(int i=t; i<N1; i+=1024){
        if(i==0){ sx[0]=meanv[b*3]; sy[0]=meanv[b*3+1]; sz[0]=meanv[b*3+2]; }
        else{
            const float* p = xyz + ((size_t)b*NPTS + (i-1))*3;
            sx[i]=p[0]; sy[i]=p[1]; sz[i]=p[2];
        }
    }
    if(t==0){ c[0]=meanv[b*3]; c[1]=meanv[b*3+1]; c[2]=meanv[b*3+2]; }
    __syncthreads();

    // register-resident copy for the hot loop
    float px[9], py[9], pz[9], dist[9];
    #pragma unroll
    for(int j=0;j<9;j++){
        int i = t + j*1024;
        if(i < N1){ px[j]=sx[i]; py[j]=sy[i]; pz[j]=sz[i]; dist[j]=1e10f; }
        else      { px[j]=0.f; py[j]=0.f; pz[j]=0.f; dist[j]=-1.0f; }
    }

    for(int s=0;s<SPTS;s++){
        float cx=c[0], cy=c[1], cz=c[2];
        if(t==0){
            float* o = newxyz + ((size_t)b*SPTS + s)*3;
            o[0]=cx; o[1]=cy; o[2]=cz;
        }
        float bv = -2.0f; int bi = 0;
        #pragma unroll
        for(int j=0;j<9;j++){
            float dx = __fadd_rn(px[j], -cx);
            float dy = __fadd_rn(py[j], -cy);
            float dz = __fadd_rn(pz[j], -cz);
            float d  = __fadd_rn(__fadd_rn(__fmul_rn(dx,dx), __fmul_rn(dy,dy)), __fmul_rn(dz,dz));
            float nd = fminf(dist[j], d);
            dist[j] = nd;
            if(nd > bv){ bv = nd; bi = t + j*1024; }
        }
        // warp reduce: max value, min index on ties
        #pragma unroll
        for(int o=16;o;o>>=1){
            float ov = __shfl_down_sync(0xffffffffu, bv, o);
            int   oi = __shfl_down_sync(0xffffffffu, bi, o);
            if(ov > bv || (ov == bv && oi < bi)){ bv = ov; bi = oi; }
        }
        if((t & 31) == 0){ sv[t>>5] = bv; si[t>>5] = bi; }
        __syncthreads();
        if(t < 32){
            bv = sv[t]; bi = si[t];
            #pragma unroll
            for(int o=16;o;o>>=1){
                float ov = __shfl_down_sync(0xffffffffu, bv, o);
                int   oi = __shfl_down_sync(0xffffffffu, bi, o);
                if(ov > bv || (ov == bv && oi < bi)){ bv = ov; bi = oi; }
            }
            if(t==0){ c[0]=sx[bi]; c[1]=sy[bi]; c[2]=sz[bi]; }
        }
        __syncthreads();
    }
}

// ---------------- feature transpose (B,C,N) -> (B,N,C) ----------------
__global__ void transpose_kernel(const float* __restrict__ f, float* __restrict__ ft){
    __shared__ float tile[32][33];
    int b = blockIdx.z;
    int n0 = blockIdx.x*32, c0 = blockIdx.y*32;
    int tx = threadIdx.x, ty = threadIdx.y;
    #pragma unroll
    for(int i=0;i<32;i+=8)
        tile[ty+i][tx] = f[((size_t)b*FEATC + (c0+ty+i))*NPTS + n0 + tx];
    __syncthreads();
    #pragma unroll
    for(int i=0;i<32;i+=8)
        ft[((size_t)b*NPTS + (n0+ty+i))*FEATC + c0 + tx] = tile[tx][ty+i];
}

// ---------------- ball query (both radii in one pass) ----------------
__global__ __launch_bounds__(256) void ballq_kernel(const float* __restrict__ xyz,
                                                    const float* __restrict__ nx,
                                                    int* __restrict__ idx0,
                                                    int* __restrict__ idx1){
    int gw = (blockIdx.x*blockDim.x + threadIdx.x) >> 5;
    int lane = threadIdx.x & 31;
    int b = gw >> 10, s = gw & 1023;
    const float R20 = (float)(0.4*0.4);
    const float R21 = (float)(0.8*0.8);
    const float* cp = nx + ((size_t)b*SPTS + s)*3;
    float cx=cp[0], cy=cp[1], cz=cp[2];
    int cnt0=0, cnt1=0, first0=0, first1=0;
    size_t base0 = ((size_t)b*SPTS + s)*NS0;
    size_t base1 = ((size_t)b*SPTS + s)*NS1;
    unsigned lmask = (1u << lane) - 1u;
    for(int ch=0; ch<NPTS/32; ch++){
        if(cnt0 >= NS0 && cnt1 >= NS1) break;
        int n = ch*32 + lane;
        const float* p = xyz + ((size_t)b*NPTS + n)*3;
        float dx = __fadd_rn(cx, -p[0]);
        float dy = __fadd_rn(cy, -p[1]);
        float dz = __fadd_rn(cz, -p[2]);
        float d2 = __fadd_rn(__fadd_rn(__fmul_rn(dx,dx), __fmul_rn(dy,dy)), __fmul_rn(dz,dz));
        unsigned m1 = __ballot_sync(0xffffffffu, d2 < R21);
        unsigned m0 = __ballot_sync(0xffffffffu, d2 < R20);
        if(m0 && cnt0 < NS0){
            if(cnt0 == 0) first0 = ch*32 + __ffs(m0) - 1;
            if((m0 >> lane) & 1){
                int r = __popc(m0 & lmask);
                if(cnt0 + r < NS0) idx0[base0 + cnt0 + r] = n;
            }
            cnt0 = min(NS0, cnt0 + __popc(m0));
        }
        if(m1 && cnt1 < NS1){
            if(cnt1 == 0) first1 = ch*32 + __ffs(m1) - 1;
            if((m1 >> lane) & 1){
                int r = __popc(m1 & lmask);
                if(cnt1 + r < NS1) idx1[base1 + cnt1 + r] = n;
            }
            cnt1 = min(NS1, cnt1 + __popc(m1));
        }
    }
    int p0 = (cnt0 > 0) ? first0 : 0;
    for(int k=cnt0+lane; k<NS0; k+=32) idx0[base0+k] = p0;
    int p1 = (cnt1 > 0) ? first1 : 0;
    for(int k=cnt1+lane; k<NS1; k+=32) idx1[base1+k] = p1;
}

// ---------------- gather: build X0 [67][M] ----------------
__global__ void gather_kernel(const float* __restrict__ xyz, const float* __restrict__ ft,
                              const float* __restrict__ nx, const int* __restrict__ idx,
                              float* __restrict__ X, int ns, int M){
    int m = blockIdx.x*blockDim.x + threadIdx.x;
    if(m >= M) return;
    int sc = m / ns;
    int s = sc & 1023, b = sc >> 10;
    int id = idx[m];
    const float* p = xyz + ((size_t)b*NPTS + id)*3;
    const float* c = nx + ((size_t)b*SPTS + s)*3;
    X[(size_t)0*M + m] = p[0]-c[0];
    X[(size_t)1*M + m] = p[1]-c[1];
    X[(size_t)2*M + m] = p[2]-c[2];
    const float4* fr = (const float4*)(ft + ((size_t)b*NPTS + id)*FEATC);
    #pragma unroll
    for(int c4=0;c4<16;c4++){
        float4 v = fr[c4];
        size_t r = (size_t)(3 + c4*4)*M + m;
        X[r] = v.x; X[r+(size_t)M] = v.y; X[r+2*(size_t)M] = v.z; X[r+3*(size_t)M] = v.w;
    }
}

// ---------------- GEMM: Y[Cout][M] = W[Cout][Cin] * transform(X[Cin][M]) ----------------
// transform(x) = relu(tsc[c]*x + tsh[c]) if tsc != null else x.
// Accumulates per-out-channel sum / sumsq into gsum / gsq (double atomics).
__global__ __launch_bounds__(256) void gemm_kernel(const float* __restrict__ W,
        const float* __restrict__ X, float* __restrict__ Y,
        int Cin, int Cout, int M,
        const float* __restrict__ tsc, const float* __restrict__ tsh,
        double* __restrict__ gsum, double* __restrict__ gsq){
    __shared__ float Wall[128*64];  // [k][o]
    __shared__ float Xs[16*128];    // [k][m]
    int tid = threadIdx.x;
    int ty = tid >> 4, tx = tid & 15;
    int m0 = blockIdx.x * 128;
    int ob = blockIdx.y * 64;
    for(int i=tid; i<128*64; i+=256){
        int k = i >> 6, o = i & 63;
        Wall[i] = (k < Cin) ? W[(size_t)(ob + o)*Cin + k] : 0.0f;
    }
    u64 acc[4][4];
    #pragma unroll
    for(int r=0;r<4;r++)
        #pragma unroll
        for(int c=0;c<4;c++) acc[r][c] = 0ull;
    int kch = (Cin + 15) >> 4;
    for(int kc=0; kc<kch; kc++){
        int rr = tid >> 4, cc = (tid & 15)*8;
        int cin = kc*16 + rr;
        float4 a = make_float4(0.f,0.f,0.f,0.f), bv = a;
        if(cin < Cin){
            const float4* p = (const float4*)(X + (size_t)cin*M + m0 + cc);
            a = p[0]; bv = p[1];
            if(tsc){
                float s_ = tsc[cin], h_ = tsh[cin];
                a.x = fmaxf(0.f, fmaf(s_, a.x, h_));
                a.y = fmaxf(0.f, fmaf(s_, a.y, h_));
                a.z = fmaxf(0.f, fmaf(s_, a.z, h_));
                a.w = fmaxf(0.f, fmaf(s_, a.w, h_));
                bv.x = fmaxf(0.f, fmaf(s_, bv.x, h_));
                bv.y = fmaxf(0.f, fmaf(s_, bv.y, h_));
                bv.z = fmaxf(0.f, fmaf(s_, bv.z, h_));
                bv.w = fmaxf(0.f, fmaf(s_, bv.w, h_));
            }
        }
        *(float4*)&Xs[rr*128 + cc]     = a;
        *(float4*)&Xs[rr*128 + cc + 4] = bv;
        __syncthreads();
        #pragma unroll
        for(int kk=0; kk<16; kk++){
            float4 w = *(const float4*)&Wall[(kc*16 + kk)*64 + ty*4];
            const ulonglong2* xp = (const ulonglong2*)&Xs[kk*128 + tx*8];
            ulonglong2 xa = xp[0], xb = xp[1];
            u64 w0 = pk2(w.x, w.x), w1 = pk2(w.y, w.y);
            u64 w2 = pk2(w.z, w.z), w3 = pk2(w.w, w.w);
            fma2(acc[0][0], w0, xa.x); fma2(acc[0][1], w0, xa.y);
            fma2(acc[0][2], w0, xb.x); fma2(acc[0][3], w0, xb.y);
            fma2(acc[1][0], w1, xa.x); fma2(acc[1][1], w1, xa.y);
            fma2(acc[1][2], w1, xb.x); fma2(acc[1][3], w1, xb.y);
            fma2(acc[2][0], w2, xa.x); fma2(acc[2][1], w2, xa.y);
            fma2(acc[2][2], w2, xb.x); fma2(acc[2][3], w2, xb.y);
            fma2(acc[3][0], w3, xa.x); fma2(acc[3][1], w3, xa.y);
            fma2(acc[3][2], w3, xb.x); fma2(acc[3][3], w3, xb.y);
        }
        __syncthreads();
    }
    // epilogue: stats + store
    #pragma unroll
    for(int r=0;r<4;r++){
        float y[8];
        #pragma unroll
        for(int c=0;c<4;c++){ float2 f = up2(acc[r][c]); y[2*c]=f.x; y[2*c+1]=f.y; }
        float s=0.f, q=0.f;
        #pragma unroll
        for(int c=0;c<8;c++){ s += y[c]; q += y[c]*y[c]; }
        #pragma unroll
        for(int o=8;o;o>>=1){
            s += __shfl_xor_sync(0xffffffffu, s, o);
            q += __shfl_xor_sync(0xffffffffu, q, o);
        }
        int orow = ob + ty*4 + r;
        if(tx == 0){
            atomicAdd(&gsum[orow], (double)s);
            atomicAdd(&gsq[orow],  (double)q);
        }
        float4* yp = (float4*)(Y + (size_t)orow*M + m0 + tx*8);
        yp[0] = make_float4(y[0], y[1], y[2], y[3]);
        yp[1] = make_float4(y[4], y[5], y[6], y[7]);
    }
}

// ---------------- finalize BN params ----------------
__global__ void finalize_kernel(const double* __restrict__ gsum, const double* __restrict__ gsq,
                                const float* __restrict__ g, const float* __restrict__ bb,
                                float* __restrict__ sc, float* __restrict__ sh,
                                int Cout, double invM){
    int o = blockIdx.x*blockDim.x + threadIdx.x;
    if(o < Cout){
        double mean = gsum[o]*invM;
        double var  = gsq[o]*invM - mean*mean;
        float s = (float)((double)g[o] / sqrt(var + 1e-5));
        sc[o] = s;
        sh[o] = fmaf(-(float)mean, s, bb[o]);
    }
}

// ---------------- BN + ReLU + maxpool, warp-per-point (coalesced) ----------------
// One warp handles one (b, co, s); lanes read consecutive elements of the
// ns-long window, reduce via shuffle.
__global__ __launch_bounds__(256) void maxpool_kernel(const float* __restrict__ Y,
                               const float* __restrict__ sc,
                               const float* __restrict__ sh, float* __restrict__ out,
                               int Cout, int ns, int M, int coff){
    int gw = (blockIdx.x*blockDim.x + threadIdx.x) >> 5;
    int lane = threadIdx.x & 31;
    int total = BATCH*Cout*SPTS;
    if(gw >= total) return;
    int s = gw & 1023;
    int co = (gw >> 10) % Cout;
    int b = gw / (Cout*SPTS);
    float s_ = sc[co], h_ = sh[co];
    const float* p = Y + (size_t)co*M + (size_t)(b*SPTS + s)*ns;
    float mx = 0.0f;  // relu >= 0 and ns >= 1, so 0 init == max over relu values
    for(int k=lane; k<ns; k+=32)
        mx = fmaxf(mx, fmaf(s_, p[k], h_));
    #pragma unroll
    for(int o=16;o;o>>=1)
        mx = fmaxf(mx, __shfl_xor_sync(0xffffffffu, mx, o));
    if(lane == 0)
        out[((size_t)(b*384 + coff + co))*SPTS + s] = mx;
}

// ---------------- launch ----------------
extern "C" void kernel_launch(void* const* d_in, const int* in_sizes, int n_in,
                              void* d_out, int out_size){
    const float* xyz  = (const float*)d_in[0];
    const float* feat = (const float*)d_in[1];
    const float *w[6], *g[6], *bb[6];
    for(int L=0; L<6; L++){
        w[L]  = (const float*)d_in[2 + L*3];
        g[L]  = (const float*)d_in[3 + L*3];
        bb[L] = (const float*)d_in[4 + L*3];
    }
    float* out = (float*)d_out;
    float* newxyz  = out;                         // (8,1024,3)
    float* outfeat = out + (size_t)BATCH*SPTS*3;  // (8,384,1024)

    void *pA,*pB,*pC,*pFT,*pM,*pI0,*pI1,*pSum,*pSq,*pSc,*pSh;
    cudaGetSymbolAddress(&pA,  d_bufA);
    cudaGetSymbolAddress(&pB,  d_bufB);
    cudaGetSymbolAddress(&pC,  d_bufC);
    cudaGetSymbolAddress(&pFT, d_featT);
    cudaGetSymbolAddress(&pM,  d_meanv);
    cudaGetSymbolAddress(&pI0, d_idx0);
    cudaGetSymbolAddress(&pI1, d_idx1);
    cudaGetSymbolAddress(&pSum,d_gsum);
    cudaGetSymbolAddress(&pSq, d_gsq);
    cudaGetSymbolAddress(&pSc, d_scl);
    cudaGetSymbolAddress(&pSh, d_shf);
    float* A  = (float*)pA;  float* Bf = (float*)pB;  float* C = (float*)pC;
    float* ft = (float*)pFT; float* mv = (float*)pM;
    int* i0 = (int*)pI0; int* i1 = (int*)pI1;
    double* gsum = (double*)pSum; double* gsq = (double*)pSq;
    float* scv = (float*)pSc; float* shv = (float*)pSh;

    static int fps_smem_set = 0;
    const int FPS_SMEM = 3*N1*sizeof(float);
    if(!fps_smem_set){
        cudaFuncSetAttribute(fps_kernel, cudaFuncAttributeMaxDynamicSharedMemorySize, FPS_SMEM);
        fps_smem_set = 1;
    }

    zero_stats_kernel<<<6,256>>>(gsum, gsq);
    mean_kernel<<<BATCH,256>>>(xyz, mv);
    fps_kernel<<<BATCH,1024,FPS_SMEM>>>(xyz, mv, newxyz);
    transpose_kernel<<<dim3(NPTS/32, FEATC/32, BATCH), dim3(32,8)>>>(feat, ft);
    ballq_kernel<<<(BATCH*SPTS)/8, 256>>>(xyz, newxyz, i0, i1);

    // ---- branch 0 (r=0.4, ns=32): 67 -> 64 -> 64 -> 128 ----
    gather_kernel<<<M0/256,256>>>(xyz, ft, newxyz, i0, C, NS0, M0);
    gemm_kernel<<<dim3(M0/128,1),256>>>(w[0], C,  A,  CIN0, 64,  M0, nullptr, nullptr, gsum+0*256, gsq+0*256);
    finalize_kernel<<<1,256>>>(gsum+0*256, gsq+0*256, g[0], bb[0], scv+0*256, shv+0*256, 64, 1.0/M0);
    gemm_kernel<<<dim3(M0/128,1),256>>>(w[1], A,  Bf, 64,   64,  M0, scv+0*256, shv+0*256, gsum+1*256, gsq+1*256);
    finalize_kernel<<<1,256>>>(gsum+1*256, gsq+1*256, g[1], bb[1], scv+1*256, shv+1*256, 64, 1.0/M0);
    gemm_kernel<<<dim3(M0/128,2),256>>>(w[2], Bf, A,  64,   128, M0, scv+1*256, shv+1*256, gsum+2*256, gsq+2*256);
    finalize_kernel<<<1,256>>>(gsum+2*256, gsq+2*256, g[2], bb[2], scv+2*256, shv+2*256, 128, 1.0/M0);
    maxpool_kernel<<<(BATCH*128*SPTS*32)/256,256>>>(A, scv+2*256, shv+2*256, outfeat, 128, NS0, M0, 0);

    // ---- branch 1 (r=0.8, ns=64): 67 -> 64 -> 128 -> 256 ----
    gather_kernel<<<M1/256,256>>>(xyz, ft, newxyz, i1, C, NS1, M1);
    gemm_kernel<<<dim3(M1/128,1),256>>>(w[3], C,  A,  CIN0, 64,  M1, nullptr, nullptr, gsum+3*256, gsq+3*256);
    finalize_kernel<<<1,256>>>(gsum+3*256, gsq+3*256, g[3], bb[3], scv+3*256, shv+3*256, 64, 1.0/M1);
    gemm_kernel<<<dim3(M1/128,2),256>>>(w[4], A,  Bf, 64,   128, M1, scv+3*256, shv+3*256, gsum+4*256, gsq+4*256);
    finalize_kernel<<<1,256>>>(gsum+4*256, gsq+4*256, g[4], bb[4], scv+4*256, shv+4*256, 128, 1.0/M1);
    gemm_kernel<<<dim3(M1/128,4),256>>>(w[5], Bf, A,  128,  256, M1, scv+4*256, shv+4*256, gsum+5*256, gsq+5*256);
    finalize_kernel<<<1,256>>>(gsum+5*256, gsq+5*256, g[5], bb[5], scv+5*256, shv+5*256, 256, 1.0/M1);
    maxpool_kernel<<<(BATCH*256*SPTS*32)/256,256>>>(A, scv+5*256, shv+5*256, outfeat, 256, NS1, M1, 128);
}

// round 7
// speedup vs baseline: 2.4490x; 1.6493x over previous
#include <cuda_runtime.h>
#include <cstdint>
#include <cstdio>

#define BATCH 8
#define NPTS 8192
#define N1 8193
#define SPTS 1024
#define FEATC 64
#define CIN0 67
#define NS0 32
#define NS1 64
#define M0 (BATCH*SPTS*NS0)   /* 262144 */
#define M1 (BATCH*SPTS*NS1)   /* 524288 */

// ---------------- static scratch (allocation is forbidden) ----------------
__device__ float  d_bufA[(size_t)256*M1];   // 537 MB  (Y0 / Y2 per branch)
__device__ float  d_bufB[(size_t)128*M1];   // 268 MB  (Y1)
__device__ float  d_bufC[(size_t)CIN0*M1];  // 140 MB  (gathered X0)
__device__ float  d_featT[(size_t)BATCH*NPTS*FEATC]; // 16.8 MB
__device__ float  d_meanv[BATCH*3];
__device__ int    d_idx0[(size_t)BATCH*SPTS*NS0];
__device__ int    d_idx1[(size_t)BATCH*SPTS*NS1];
__device__ float  d_gsum[6*256];
__device__ float  d_gsq [6*256];
__device__ float  d_scl [6*256];
__device__ float  d_shf [6*256];

// ---------------- tf32 helpers ----------------
__device__ __forceinline__ float tf32r(float x){
    unsigned u; asm("cvt.rna.tf32.f32 %0, %1;" : "=r"(u) : "f"(x));
    return __uint_as_float(u);
}
__device__ __forceinline__ void mma8(float* c, const float* a, const float* b){
    asm volatile("mma.sync.aligned.m16n8k8.row.col.f32.tf32.tf32.f32 "
      "{%0,%1,%2,%3},{%4,%5,%6,%7},{%8,%9},{%0,%1,%2,%3};"
      : "+f"(c[0]),"+f"(c[1]),"+f"(c[2]),"+f"(c[3])
      : "r"(__float_as_uint(a[0])),"r"(__float_as_uint(a[1])),
        "r"(__float_as_uint(a[2])),"r"(__float_as_uint(a[3])),
        "r"(__float_as_uint(b[0])),"r"(__float_as_uint(b[1])));
}

// ---------------- zero stats ----------------
__global__ void zero_stats_kernel(float* gsum, float* gsq){
    int i = blockIdx.x*blockDim.x + threadIdx.x;
    if(i < 6*256){ gsum[i]=0.f; gsq[i]=0.f; }
}

// ---------------- mean over points ----------------
__global__ void mean_kernel(const float* __restrict__ xyz, float* __restrict__ meanv){
    int b = blockIdx.x, t = threadIdx.x;
    double sx=0, sy=0, sz=0;
    for(int n=t; n<NPTS; n+=256){
        const float* p = xyz + ((size_t)b*NPTS + n)*3;
        sx += (double)p[0]; sy += (double)p[1]; sz += (double)p[2];
    }
    __shared__ double rx[256], ry[256], rz[256];
    rx[t]=sx; ry[t]=sy; rz[t]=sz; __syncthreads();
    for(int o=128;o;o>>=1){
        if(t<o){ rx[t]+=rx[t+o]; ry[t]+=ry[t+o]; rz[t]+=rz[t+o]; }
        __syncthreads();
    }
    if(t==0){
        meanv[b*3+0]=(float)(rx[0]/NPTS);
        meanv[b*3+1]=(float)(ry[0]/NPTS);
        meanv[b*3+2]=(float)(rz[0]/NPTS);
    }
}

// ---------------- farthest point sampling ----------------
// Registers for the hot loop (compile-time indices only), shared for the
// centroid fetch. Exact reference arithmetic: no FMA contraction, sum order
// ((dx2+dy2)+dz2), first-occurrence argmax (min index on ties).
__global__ __launch_bounds__(1024) void fps_kernel(const float* __restrict__ xyz,
                                                   const float* __restrict__ meanv,
                                                   float* __restrict__ newxyz){
    extern __shared__ float sh[];          // sx[N1], sy[N1], sz[N1]
    float* sx = sh;
    float* sy = sh + N1;
    float* sz = sh + 2*N1;
    __shared__ float c[3];
    __shared__ float sv[32]; __shared__ int si[32];
    int b = blockIdx.x, t = threadIdx.x;

    for(int i=t; i<N1; i+=1024){
        if(i==0){ sx[0]=meanv[b*3]; sy[0]=meanv[b*3+1]; sz[0]=meanv[b*3+2]; }
        else{
            const float* p = xyz + ((size_t)b*NPTS + (i-1))*3;
            sx[i]=p[0]; sy[i]=p[1]; sz[i]=p[2];
        }
    }
    if(t==0){ c[0]=meanv[b*3]; c[1]=meanv[b*3+1]; c[2]=meanv[b*3+2]; }
    __syncthreads();

    float px[9], py[9], pz[9], dist[9];
    #pragma unroll
    for(int j=0;j<9;j++){
        int i = t + j*1024;
        if(i < N1){ px[j]=sx[i]; py[j]=sy[i]; pz[j]=sz[i]; dist[j]=1e10f; }
        else      { px[j]=0.f; py[j]=0.f; pz[j]=0.f; dist[j]=-1.0f; }
    }

    for(int s=0;s<SPTS;s++){
        float cx=c[0], cy=c[1], cz=c[2];
        if(t==0){
            float* o = newxyz + ((size_t)b*SPTS + s)*3;
            o[0]=cx; o[1]=cy; o[2]=cz;
        }
        float bv = -2.0f; int bi = 0;
        #pragma unroll
        for(int j=0;j<9;j++){
            float dx = __fadd_rn(px[j], -cx);
            float dy = __fadd_rn(py[j], -cy);
            float dz = __fadd_rn(pz[j], -cz);
            float d  = __fadd_rn(__fadd_rn(__fmul_rn(dx,dx), __fmul_rn(dy,dy)), __fmul_rn(dz,dz));
            float nd = fminf(dist[j], d);
            dist[j] = nd;
            if(nd > bv){ bv = nd; bi = t + j*1024; }
        }
        #pragma unroll
        for(int o=16;o;o>>=1){
            float ov = __shfl_down_sync(0xffffffffu, bv, o);
            int   oi = __shfl_down_sync(0xffffffffu, bi, o);
            if(ov > bv || (ov == bv && oi < bi)){ bv = ov; bi = oi; }
        }
        if((t & 31) == 0){ sv[t>>5] = bv; si[t>>5] = bi; }
        __syncthreads();
        if(t < 32){
            bv = sv[t]; bi = si[t];
            #pragma unroll
            for(int o=16;o;o>>=1){
                float ov = __shfl_down_sync(0xffffffffu, bv, o);
                int   oi = __shfl_down_sync(0xffffffffu, bi, o);
                if(ov > bv || (ov == bv && oi < bi)){ bv = ov; bi = oi; }
            }
            if(t==0){ c[0]=sx[bi]; c[1]=sy[bi]; c[2]=sz[bi]; }
        }
        __syncthreads();
    }
}

// ---------------- feature transpose (B,C,N) -> (B,N,C) ----------------
__global__ void transpose_kernel(const float* __restrict__ f, float* __restrict__ ft){
    __shared__ float tile[32][33];
    int b = blockIdx.z;
    int n0 = blockIdx.x*32, c0 = blockIdx.y*32;
    int tx = threadIdx.x, ty = threadIdx.y;
    #pragma unroll
    for(int i=0;i<32;i+=8)
        tile[ty+i][tx] = f[((size_t)b*FEATC + (c0+ty+i))*NPTS + n0 + tx];
    __syncthreads();
    #pragma unroll
    for(int i=0;i<32;i+=8)
        ft[((size_t)b*NPTS + (n0+ty+i))*FEATC + c0 + tx] = tile[tx][ty+i];
}

// ---------------- ball query (both radii in one pass) ----------------
__global__ __launch_bounds__(256) void ballq_kernel(const float* __restrict__ xyz,
                                                    const float* __restrict__ nx,
                                                    int* __restrict__ idx0,
                                                    int* __restrict__ idx1){
    int gw = (blockIdx.x*blockDim.x + threadIdx.x) >> 5;
    int lane = threadIdx.x & 31;
    int b = gw >> 10, s = gw & 1023;
    const float R20 = (float)(0.4*0.4);
    const float R21 = (float)(0.8*0.8);
    const float* cp = nx + ((size_t)b*SPTS + s)*3;
    float cx=cp[0], cy=cp[1], cz=cp[2];
    int cnt0=0, cnt1=0, first0=0, first1=0;
    size_t base0 = ((size_t)b*SPTS + s)*NS0;
    size_t base1 = ((size_t)b*SPTS + s)*NS1;
    unsigned lmask = (1u << lane) - 1u;
    for(int ch=0; ch<NPTS/32; ch++){
        if(cnt0 >= NS0 && cnt1 >= NS1) break;
        int n = ch*32 + lane;
        const float* p = xyz + ((size_t)b*NPTS + n)*3;
        float dx = __fadd_rn(cx, -p[0]);
        float dy = __fadd_rn(cy, -p[1]);
        float dz = __fadd_rn(cz, -p[2]);
        float d2 = __fadd_rn(__fadd_rn(__fmul_rn(dx,dx), __fmul_rn(dy,dy)), __fmul_rn(dz,dz));
        unsigned m1 = __ballot_sync(0xffffffffu, d2 < R21);
        unsigned m0 = __ballot_sync(0xffffffffu, d2 < R20);
        if(m0 && cnt0 < NS0){
            if(cnt0 == 0) first0 = ch*32 + __ffs(m0) - 1;
            if((m0 >> lane) & 1){
                int r = __popc(m0 & lmask);
                if(cnt0 + r < NS0) idx0[base0 + cnt0 + r] = n;
            }
            cnt0 = min(NS0, cnt0 + __popc(m0));
        }
        if(m1 && cnt1 < NS1){
            if(cnt1 == 0) first1 = ch*32 + __ffs(m1) - 1;
            if((m1 >> lane) & 1){
                int r = __popc(m1 & lmask);
                if(cnt1 + r < NS1) idx1[base1 + cnt1 + r] = n;
            }
            cnt1 = min(NS1, cnt1 + __popc(m1));
        }
    }
    int p0 = (cnt0 > 0) ? first0 : 0;
    for(int k=cnt0+lane; k<NS0; k+=32) idx0[base0+k] = p0;
    int p1 = (cnt1 > 0) ? first1 : 0;
    for(int k=cnt1+lane; k<NS1; k+=32) idx1[base1+k] = p1;
}

// ---------------- gather: build X0 [67][M] ----------------
__global__ void gather_kernel(const float* __restrict__ xyz, const float* __restrict__ ft,
                              const float* __restrict__ nx, const int* __restrict__ idx,
                              float* __restrict__ X, int ns, int M){
    int m = blockIdx.x*blockDim.x + threadIdx.x;
    if(m >= M) return;
    int sc = m / ns;
    int s = sc & 1023, b = sc >> 10;
    int id = idx[m];
    const float* p = xyz + ((size_t)b*NPTS + id)*3;
    const float* c = nx + ((size_t)b*SPTS + s)*3;
    X[(size_t)0*M + m] = p[0]-c[0];
    X[(size_t)1*M + m] = p[1]-c[1];
    X[(size_t)2*M + m] = p[2]-c[2];
    const float4* fr = (const float4*)(ft + ((size_t)b*NPTS + id)*FEATC);
    #pragma unroll
    for(int c4=0;c4<16;c4++){
        float4 v = fr[c4];
        size_t r = (size_t)(3 + c4*4)*M + m;
        X[r] = v.x; X[r+(size_t)M] = v.y; X[r+2*(size_t)M] = v.z; X[r+3*(size_t)M] = v.w;
    }
}

// ---------------- tensor-core GEMM ----------------
// Y[Cout][M] = W[Cout][Cin] * transform(X[Cin][M]),
// transform(x) = relu(tsc[c]*x + tsh[c]) if tsc else x; inputs tf32-rounded.
// Block tile: 64 (Cout) x 256 (M), 8 warps each owning a 64x32 warp tile.
// Per-channel sum/sumsq of Y reduced in smem, one float atomic per channel/block.
__global__ __launch_bounds__(256) void gemm_tc_kernel(const float* __restrict__ W,
        const float* __restrict__ X, float* __restrict__ Y,
        int Cin, int Cout, int M,
        const float* __restrict__ tsc, const float* __restrict__ tsh,
        float* __restrict__ gsum, float* __restrict__ gsq){
    __shared__ float Xs[16*264];   // [k][m], stride 264 (%32==8 -> conflict-free B frags)
    __shared__ float Wc[64*20];    // [o][k], stride 20  (conflict-free A frags)
    __shared__ float ssum[64], ssq[64];
    int tid = threadIdx.x;
    int lane = tid & 31, wn = tid >> 5;
    int g = lane >> 2, tg = lane & 3;
    int ob = blockIdx.x * 64;
    int m0 = blockIdx.y * 256;
    if(tid < 64){ ssum[tid]=0.f; ssq[tid]=0.f; }

    float acc[4][4][4];
    #pragma unroll
    for(int mt=0;mt<4;mt++)
        #pragma unroll
        for(int nt=0;nt<4;nt++)
            #pragma unroll
            for(int i=0;i<4;i++) acc[mt][nt][i]=0.f;

    int kchunks = (Cin + 15) >> 4;
    for(int kc=0; kc<kchunks; kc++){
        int kb = kc*16;
        // ---- stage X chunk (BN+ReLU fused, tf32 rounding) ----
        {
            int rr = tid >> 4, cb = (tid & 15)*16;
            int cin = kb + rr;
            float v[16];
            if(cin < Cin){
                const float4* p = (const float4*)(X + (size_t)cin*M + m0 + cb);
                #pragma unroll
                for(int j=0;j<4;j++){
                    float4 q = p[j];
                    v[4*j+0]=q.x; v[4*j+1]=q.y; v[4*j+2]=q.z; v[4*j+3]=q.w;
                }
                if(tsc){
                    float s_ = tsc[cin], h_ = tsh[cin];
                    #pragma unroll
                    for(int j=0;j<16;j++) v[j] = fmaxf(0.f, fmaf(s_, v[j], h_));
                }
                #pragma unroll
                for(int j=0;j<16;j++) v[j] = tf32r(v[j]);
            } else {
                #pragma unroll
                for(int j=0;j<16;j++) v[j]=0.f;
            }
            #pragma unroll
            for(int j=0;j<16;j++) Xs[rr*264 + cb + j] = v[j];
        }
        // ---- stage W chunk ----
        #pragma unroll
        for(int i=0;i<4;i++){
            int idx = tid + i*256;
            int o = idx >> 4, k = idx & 15;
            float wv = (kb + k < Cin) ? W[(size_t)(ob+o)*Cin + kb + k] : 0.f;
            Wc[o*20 + k] = tf32r(wv);
        }
        __syncthreads();
        // ---- 2 k8 steps ----
        #pragma unroll
        for(int s8=0; s8<2; s8++){
            int ko = s8*8;
            float a[4][4], b[4][2];
            #pragma unroll
            for(int mt=0;mt<4;mt++){
                int r0 = (mt*16 + g)*20 + ko + tg;
                a[mt][0] = Wc[r0];
                a[mt][1] = Wc[r0 + 160];      // row +8
                a[mt][2] = Wc[r0 + 4];        // k +4
                a[mt][3] = Wc[r0 + 164];
            }
            #pragma unroll
            for(int nt=0;nt<4;nt++){
                int cb = wn*32 + nt*8 + g;
                b[nt][0] = Xs[(ko+tg)*264 + cb];
                b[nt][1] = Xs[(ko+tg+4)*264 + cb];
            }
            #pragma unroll
            for(int mt=0;mt<4;mt++)
                #pragma unroll
                for(int nt=0;nt<4;nt++)
                    mma8(acc[mt][nt], a[mt], b[nt]);
        }
        __syncthreads();
    }

    // ---- epilogue: stats + store ----
    float s8v[8], q8v[8];
    #pragma unroll
    for(int i=0;i<8;i++){ s8v[i]=0.f; q8v[i]=0.f; }
    #pragma unroll
    for(int mt=0;mt<4;mt++){
        #pragma unroll
        for(int nt=0;nt<4;nt++){
            float c0=acc[mt][nt][0], c1=acc[mt][nt][1];
            float c2=acc[mt][nt][2], c3=acc[mt][nt][3];
            s8v[mt*2+0] += c0+c1; q8v[mt*2+0] += c0*c0 + c1*c1;
            s8v[mt*2+1] += c2+c3; q8v[mt*2+1] += c2*c2 + c3*c3;
        }
    }
    #pragma unroll
    for(int i=0;i<8;i++){
        s8v[i] += __shfl_xor_sync(0xffffffffu, s8v[i], 1);
        s8v[i] += __shfl_xor_sync(0xffffffffu, s8v[i], 2);
        q8v[i] += __shfl_xor_sync(0xffffffffu, q8v[i], 1);
        q8v[i] += __shfl_xor_sync(0xffffffffu, q8v[i], 2);
    }
    if(tg == 0){
        #pragma unroll
        for(int mt=0;mt<4;mt++){
            atomicAdd(&ssum[mt*16 + g],     s8v[mt*2+0]);
            atomicAdd(&ssq [mt*16 + g],     q8v[mt*2+0]);
            atomicAdd(&ssum[mt*16 + g + 8], s8v[mt*2+1]);
            atomicAdd(&ssq [mt*16 + g + 8], q8v[mt*2+1]);
        }
    }
    // store Y
    #pragma unroll
    for(int mt=0;mt<4;mt++){
        #pragma unroll
        for(int nt=0;nt<4;nt++){
            int m = m0 + wn*32 + nt*8 + 2*tg;
            int r0 = ob + mt*16 + g;
            *(float2*)(Y + (size_t)r0*M + m)     = make_float2(acc[mt][nt][0], acc[mt][nt][1]);
            *(float2*)(Y + (size_t)(r0+8)*M + m) = make_float2(acc[mt][nt][2], acc[mt][nt][3]);
        }
    }
    __syncthreads();
    if(tid < 64){
        atomicAdd(&gsum[ob + tid], ssum[tid]);
        atomicAdd(&gsq [ob + tid], ssq [tid]);
    }
}

// ---------------- finalize BN params ----------------
__global__ void finalize_kernel(const float* __restrict__ gsum, const float* __restrict__ gsq,
                                const float* __restrict__ g, const float* __restrict__ bb,
                                float* __restrict__ sc, float* __restrict__ sh,
                                int Cout, double invM){
    int o = blockIdx.x*blockDim.x + threadIdx.x;
    if(o < Cout){
        double mean = (double)gsum[o]*invM;
        double var  = (double)gsq[o]*invM - mean*mean;
        float s = (float)((double)g[o] / sqrt(var + 1e-5));
        sc[o] = s;
        sh[o] = fmaf(-(float)mean, s, bb[o]);
    }
}

// ---------------- BN + ReLU + maxpool, warp-per-point (coalesced) ----------------
__global__ __launch_bounds__(256) void maxpool_kernel(const float* __restrict__ Y,
                               const float* __restrict__ sc,
                               const float* __restrict__ sh, float* __restrict__ out,
                               int Cout, int ns, int M, int coff){
    int gw = (blockIdx.x*blockDim.x + threadIdx.x) >> 5;
    int lane = threadIdx.x & 31;
    int total = BATCH*Cout*SPTS;
    if(gw >= total) return;
    int s = gw & 1023;
    int co = (gw >> 10) % Cout;
    int b = gw / (Cout*SPTS);
    float s_ = sc[co], h_ = sh[co];
    const float* p = Y + (size_t)co*M + (size_t)(b*SPTS + s)*ns;
    float mx = 0.0f;  // relu >= 0 and ns >= 1
    for(int k=lane; k<ns; k+=32)
        mx = fmaxf(mx, fmaf(s_, p[k], h_));
    #pragma unroll
    for(int o=16;o;o>>=1)
        mx = fmaxf(mx, __shfl_xor_sync(0xffffffffu, mx, o));
    if(lane == 0)
        out[((size_t)(b*384 + coff + co))*SPTS + s] = mx;
}

// ---------------- launch ----------------
extern "C" void kernel_launch(void* const* d_in, const int* in_sizes, int n_in,
                              void* d_out, int out_size){
    const float* xyz  = (const float*)d_in[0];
    const float* feat = (const float*)d_in[1];
    const float *w[6], *g[6], *bb[6];
    for(int L=0; L<6; L++){
        w[L]  = (const float*)d_in[2 + L*3];
        g[L]  = (const float*)d_in[3 + L*3];
        bb[L] = (const float*)d_in[4 + L*3];
    }
    float* out = (float*)d_out;
    float* newxyz  = out;                         // (8,1024,3)
    float* outfeat = out + (size_t)BATCH*SPTS*3;  // (8,384,1024)

    void *pA,*pB,*pC,*pFT,*pM,*pI0,*pI1,*pSum,*pSq,*pSc,*pSh;
    cudaGetSymbolAddress(&pA,  d_bufA);
    cudaGetSymbolAddress(&pB,  d_bufB);
    cudaGetSymbolAddress(&pC,  d_bufC);
    cudaGetSymbolAddress(&pFT, d_featT);
    cudaGetSymbolAddress(&pM,  d_meanv);
    cudaGetSymbolAddress(&pI0, d_idx0);
    cudaGetSymbolAddress(&pI1, d_idx1);
    cudaGetSymbolAddress(&pSum,d_gsum);
    cudaGetSymbolAddress(&pSq, d_gsq);
    cudaGetSymbolAddress(&pSc, d_scl);
    cudaGetSymbolAddress(&pSh, d_shf);
    float* A  = (float*)pA;  float* Bf = (float*)pB;  float* C = (float*)pC;
    float* ft = (float*)pFT; float* mv = (float*)pM;
    int* i0 = (int*)pI0; int* i1 = (int*)pI1;
    float* gsum = (float*)pSum; float* gsq = (float*)pSq;
    float* scv = (float*)pSc; float* shv = (float*)pSh;

    static int fps_smem_set = 0;
    const int FPS_SMEM = 3*N1*sizeof(float);
    if(!fps_smem_set){
        cudaFuncSetAttribute(fps_kernel, cudaFuncAttributeMaxDynamicSharedMemorySize, FPS_SMEM);
        fps_smem_set = 1;
    }

    zero_stats_kernel<<<6,256>>>(gsum, gsq);
    mean_kernel<<<BATCH,256>>>(xyz, mv);
    fps_kernel<<<BATCH,1024,FPS_SMEM>>>(xyz, mv, newxyz);
    transpose_kernel<<<dim3(NPTS/32, FEATC/32, BATCH), dim3(32,8)>>>(feat, ft);
    ballq_kernel<<<(BATCH*SPTS)/8, 256>>>(xyz, newxyz, i0, i1);

    // ---- branch 0 (r=0.4, ns=32): 67 -> 64 -> 64 -> 128 ----
    gather_kernel<<<M0/256,256>>>(xyz, ft, newxyz, i0, C, NS0, M0);
    gemm_tc_kernel<<<dim3(1, M0/256),256>>>(w[0], C,  A,  CIN0, 64,  M0, nullptr, nullptr, gsum+0*256, gsq+0*256);
    finalize_kernel<<<1,256>>>(gsum+0*256, gsq+0*256, g[0], bb[0], scv+0*256, shv+0*256, 64, 1.0/M0);
    gemm_tc_kernel<<<dim3(1, M0/256),256>>>(w[1], A,  Bf, 64,   64,  M0, scv+0*256, shv+0*256, gsum+1*256, gsq+1*256);
    finalize_kernel<<<1,256>>>(gsum+1*256, gsq+1*256, g[1], bb[1], scv+1*256, shv+1*256, 64, 1.0/M0);
    gemm_tc_kernel<<<dim3(2, M0/256),256>>>(w[2], Bf, A,  64,   128, M0, scv+1*256, shv+1*256, gsum+2*256, gsq+2*256);
    finalize_kernel<<<1,256>>>(gsum+2*256, gsq+2*256, g[2], bb[2], scv+2*256, shv+2*256, 128, 1.0/M0);
    maxpool_kernel<<<(BATCH*128*SPTS*32)/256,256>>>(A, scv+2*256, shv+2*256, outfeat, 128, NS0, M0, 0);

    // ---- branch 1 (r=0.8, ns=64): 67 -> 64 -> 128 -> 256 ----
    gather_kernel<<<M1/256,256>>>(xyz, ft, newxyz, i1, C, NS1, M1);
    gemm_tc_kernel<<<dim3(1, M1/256),256>>>(w[3], C,  A,  CIN0, 64,  M1, nullptr, nullptr, gsum+3*256, gsq+3*256);
    finalize_kernel<<<1,256>>>(gsum+3*256, gsq+3*256, g[3], bb[3], scv+3*256, shv+3*256, 64, 1.0/M1);
    gemm_tc_kernel<<<dim3(2, M1/256),256>>>(w[4], A,  Bf, 64,   128, M1, scv+3*256, shv+3*256, gsum+4*256, gsq+4*256);
    finalize_kernel<<<1,256>>>(gsum+4*256, gsq+4*256, g[4], bb[4], scv+4*256, shv+4*256, 128, 1.0/M1);
    gemm_tc_kernel<<<dim3(4, M1/256),256>>>(w[5], Bf, A,  128,  256, M1, scv+4*256, shv+4*256, gsum+5*256, gsq+5*256);
    finalize_kernel<<<1,256>>>(gsum+5*256, gsq+5*256, g[5], bb[5], scv+5*256, shv+5*256, 256, 1.0/M1);
    maxpool_kernel<<<(BATCH*256*SPTS*32)/256,256>>>(A, scv+5*256, shv+5*256, outfeat, 256, NS1, M1, 128);
}

// round 10
// speedup vs baseline: 3.1986x; 1.3061x over previous
#include <cuda_runtime.h>
#include <cstdint>
#include <cstdio>

#define BATCH 8
#define NPTS 8192
#define N1 8193
#define SPTS 1024
#define FEATC 64
#define CIN0 67
#define NS0 32
#define NS1 64
#define M0 (BATCH*SPTS*NS0)   /* 262144 */
#define M1 (BATCH*SPTS*NS1)   /* 524288 */
#define NWIN 8192             /* M0/NS0 == M1/NS1 */

// ---------------- static scratch (allocation is forbidden) ----------------
__device__ float  d_bufA[(size_t)64*M1];    // 134 MB  (Y0 per branch)
__device__ float  d_bufB[(size_t)128*M1];   // 268 MB  (Y1 per branch)
__device__ float  d_featT[(size_t)BATCH*NPTS*FEATC]; // 16.8 MB
__device__ float  d_pmax[(size_t)256*NWIN]; // 8 MB pooled raw max
__device__ float  d_pmin[(size_t)256*NWIN]; // 8 MB pooled raw min
__device__ float  d_meanv[BATCH*3];
__device__ int    d_idx0[(size_t)BATCH*SPTS*NS0];
__device__ int    d_idx1[(size_t)BATCH*SPTS*NS1];
__device__ float  d_gsum[6*256];
__device__ float  d_gsq [6*256];
__device__ float  d_scl [6*256];
__device__ float  d_shf [6*256];

// ---------------- tf32 helpers ----------------
__device__ __forceinline__ float tf32r(float x){
    unsigned u; asm("cvt.rna.tf32.f32 %0, %1;" : "=r"(u) : "f"(x));
    return __uint_as_float(u);
}
__device__ __forceinline__ void mma8(float* c, const float* a, const float* b){
    asm volatile("mma.sync.aligned.m16n8k8.row.col.f32.tf32.tf32.f32 "
      "{%0,%1,%2,%3},{%4,%5,%6,%7},{%8,%9},{%0,%1,%2,%3};"
      : "+f"(c[0]),"+f"(c[1]),"+f"(c[2]),"+f"(c[3])
      : "r"(__float_as_uint(a[0])),"r"(__float_as_uint(a[1])),
        "r"(__float_as_uint(a[2])),"r"(__float_as_uint(a[3])),
        "r"(__float_as_uint(b[0])),"r"(__float_as_uint(b[1])));
}

// ---------------- zero stats ----------------
__global__ void zero_stats_kernel(float* gsum, float* gsq){
    int i = blockIdx.x*blockDim.x + threadIdx.x;
    if(i < 6*256){ gsum[i]=0.f; gsq[i]=0.f; }
}

// ---------------- mean over points ----------------
__global__ void mean_kernel(const float* __restrict__ xyz, float* __restrict__ meanv){
    int b = blockIdx.x, t = threadIdx.x;
    double sx=0, sy=0, sz=0;
    for(int n=t; n<NPTS; n+=256){
        const float* p = xyz + ((size_t)b*NPTS + n)*3;
        sx += (double)p[0]; sy += (double)p[1]; sz += (double)p[2];
    }
    __shared__ double rx[256], ry[256], rz[256];
    rx[t]=sx; ry[t]=sy; rz[t]=sz; __syncthreads();
    for(int o=128;o;o>>=1){
        if(t<o){ rx[t]+=rx[t+o]; ry[t]+=ry[t+o]; rz[t]+=rz[t+o]; }
        __syncthreads();
    }
    if(t==0){
        meanv[b*3+0]=(float)(rx[0]/NPTS);
        meanv[b*3+1]=(float)(ry[0]/NPTS);
        meanv[b*3+2]=(float)(rz[0]/NPTS);
    }
}

// ---------------- farthest point sampling ----------------
// Registers for the hot loop, shared for the centroid fetch.
// Exact reference arithmetic: no FMA contraction, sum order ((dx2+dy2)+dz2),
// first-occurrence argmax (min index on ties).
__global__ __launch_bounds__(1024) void fps_kernel(const float* __restrict__ xyz,
                                                   const float* __restrict__ meanv,
                                                   float* __restrict__ newxyz){
    extern __shared__ float sh[];          // sx[N1], sy[N1], sz[N1]
    float* sx = sh;
    float* sy = sh + N1;
    float* sz = sh + 2*N1;
    __shared__ float c[3];
    __shared__ float sv[32]; __shared__ int si[32];
    int b = blockIdx.x, t = threadIdx.x;

    for(int i=t; i<N1; i+=1024){
        if(i==0){ sx[0]=meanv[b*3]; sy[0]=meanv[b*3+1]; sz[0]=meanv[b*3+2]; }
        else{
            const float* p = xyz + ((size_t)b*NPTS + (i-1))*3;
            sx[i]=p[0]; sy[i]=p[1]; sz[i]=p[2];
        }
    }
    if(t==0){ c[0]=meanv[b*3]; c[1]=meanv[b*3+1]; c[2]=meanv[b*3+2]; }
    __syncthreads();

    float px[9], py[9], pz[9], dist[9];
    #pragma unroll
    for(int j=0;j<9;j++){
        int i = t + j*1024;
        if(i < N1){ px[j]=sx[i]; py[j]=sy[i]; pz[j]=sz[i]; dist[j]=1e10f; }
        else      { px[j]=0.f; py[j]=0.f; pz[j]=0.f; dist[j]=-1.0f; }
    }

    for(int s=0;s<SPTS;s++){
        float cx=c[0], cy=c[1], cz=c[2];
        if(t==0){
            float* o = newxyz + ((size_t)b*SPTS + s)*3;
            o[0]=cx; o[1]=cy; o[2]=cz;
        }
        float bv = -2.0f; int bi = 0;
        #pragma unroll
        for(int j=0;j<9;j++){
            float dx = __fadd_rn(px[j], -cx);
            float dy = __fadd_rn(py[j], -cy);
            float dz = __fadd_rn(pz[j], -cz);
            float d  = __fadd_rn(__fadd_rn(__fmul_rn(dx,dx), __fmul_rn(dy,dy)), __fmul_rn(dz,dz));
            float nd = fminf(dist[j], d);
            dist[j] = nd;
            if(nd > bv){ bv = nd; bi = t + j*1024; }
        }
        #pragma unroll
        for(int o=16;o;o>>=1){
            float ov = __shfl_down_sync(0xffffffffu, bv, o);
            int   oi = __shfl_down_sync(0xffffffffu, bi, o);
            if(ov > bv || (ov == bv && oi < bi)){ bv = ov; bi = oi; }
        }
        if((t & 31) == 0){ sv[t>>5] = bv; si[t>>5] = bi; }
        __syncthreads();
        if(t < 32){
            bv = sv[t]; bi = si[t];
            #pragma unroll
            for(int o=16;o;o>>=1){
                float ov = __shfl_down_sync(0xffffffffu, bv, o);
                int   oi = __shfl_down_sync(0xffffffffu, bi, o);
                if(ov > bv || (ov == bv && oi < bi)){ bv = ov; bi = oi; }
            }
            if(t==0){ c[0]=sx[bi]; c[1]=sy[bi]; c[2]=sz[bi]; }
        }
        __syncthreads();
    }
}

// ---------------- feature transpose (B,C,N) -> (B,N,C) ----------------
__global__ void transpose_kernel(const float* __restrict__ f, float* __restrict__ ft){
    __shared__ float tile[32][33];
    int b = blockIdx.z;
    int n0 = blockIdx.x*32, c0 = blockIdx.y*32;
    int tx = threadIdx.x, ty = threadIdx.y;
    #pragma unroll
    for(int i=0;i<32;i+=8)
        tile[ty+i][tx] = f[((size_t)b*FEATC + (c0+ty+i))*NPTS + n0 + tx];
    __syncthreads();
    #pragma unroll
    for(int i=0;i<32;i+=8)
        ft[((size_t)b*NPTS + (n0+ty+i))*FEATC + c0 + tx] = tile[tx][ty+i];
}

// ---------------- ball query (both radii in one pass) ----------------
__global__ __launch_bounds__(256) void ballq_kernel(const float* __restrict__ xyz,
                                                    const float* __restrict__ nx,
                                                    int* __restrict__ idx0,
                                                    int* __restrict__ idx1){
    int gw = (blockIdx.x*blockDim.x + threadIdx.x) >> 5;
    int lane = threadIdx.x & 31;
    int b = gw >> 10, s = gw & 1023;
    const float R20 = (float)(0.4*0.4);
    const float R21 = (float)(0.8*0.8);
    const float* cp = nx + ((size_t)b*SPTS + s)*3;
    float cx=cp[0], cy=cp[1], cz=cp[2];
    int cnt0=0, cnt1=0, first0=0, first1=0;
    size_t base0 = ((size_t)b*SPTS + s)*NS0;
    size_t base1 = ((size_t)b*SPTS + s)*NS1;
    unsigned lmask = (1u << lane) - 1u;
    for(int ch=0; ch<NPTS/32; ch++){
        if(cnt0 >= NS0 && cnt1 >= NS1) break;
        int n = ch*32 + lane;
        const float* p = xyz + ((size_t)b*NPTS + n)*3;
        float dx = __fadd_rn(cx, -p[0]);
        float dy = __fadd_rn(cy, -p[1]);
        float dz = __fadd_rn(cz, -p[2]);
        float d2 = __fadd_rn(__fadd_rn(__fmul_rn(dx,dx), __fmul_rn(dy,dy)), __fmul_rn(dz,dz));
        unsigned m1 = __ballot_sync(0xffffffffu, d2 < R21);
        unsigned m0 = __ballot_sync(0xffffffffu, d2 < R20);
        if(m0 && cnt0 < NS0){
            if(cnt0 == 0) first0 = ch*32 + __ffs(m0) - 1;
            if((m0 >> lane) & 1){
                int r = __popc(m0 & lmask);
                if(cnt0 + r < NS0) idx0[base0 + cnt0 + r] = n;
            }
            cnt0 = min(NS0, cnt0 + __popc(m0));
        }
        if(m1 && cnt1 < NS1){
            if(cnt1 == 0) first1 = ch*32 + __ffs(m1) - 1;
            if((m1 >> lane) & 1){
                int r = __popc(m1 & lmask);
                if(cnt1 + r < NS1) idx1[base1 + cnt1 + r] = n;
            }
            cnt1 = min(NS1, cnt1 + __popc(m1));
        }
    }
    int p0 = (cnt0 > 0) ? first0 : 0;
    for(int k=cnt0+lane; k<NS0; k+=32) idx0[base0+k] = p0;
    int p1 = (cnt1 > 0) ? first1 : 0;
    for(int k=cnt1+lane; k<NS1; k+=32) idx1[base1+k] = p1;
}

// ==================================================================
// Fused gather + tensor-core GEMM (layer 0 of each branch).
// Stages the full 67x256 X tile in dynamic smem directly from ft/xyz via
// the ball-query indices. Cout = 64 (grid.x == 1). Writes Y + stats.
// ==================================================================
#define GX_STRIDE 264
#define GX_ROWS   80          /* 5 chunks of 16 (67 padded) */
#define G_SMEM    ((GX_ROWS*GX_STRIDE + 64*20)*4)

__global__ __launch_bounds__(256) void gemm_g_kernel(const float* __restrict__ W,
        const float* __restrict__ xyz, const float* __restrict__ ft,
        const float* __restrict__ nx, const int* __restrict__ idx,
        float* __restrict__ Y, int M, int ns,
        float* __restrict__ gsum, float* __restrict__ gsq){
    extern __shared__ float dsm[];
    float* Xs = dsm;                       // [80][264]
    float* Wc = dsm + GX_ROWS*GX_STRIDE;   // [64][20]
    __shared__ float ssum[64], ssq[64];
    int tid = threadIdx.x;
    int lane = tid & 31, wn = tid >> 5;
    int g = lane >> 2, tg = lane & 3;
    int m0 = blockIdx.y * 256;
    if(tid < 64){ ssum[tid]=0.f; ssq[tid]=0.f; }

    // ---- stage full X tile: one thread per m-column ----
    {
        int m = m0 + tid;
        int sc_ = m / ns;
        int s = sc_ & 1023, b = sc_ >> 10;
        int id = idx[m];
        const float* p = xyz + ((size_t)b*NPTS + id)*3;
        const float* c = nx  + ((size_t)b*SPTS + s)*3;
        Xs[0*GX_STRIDE + tid] = tf32r(p[0]-c[0]);
        Xs[1*GX_STRIDE + tid] = tf32r(p[1]-c[1]);
        Xs[2*GX_STRIDE + tid] = tf32r(p[2]-c[2]);
        const float4* fr = (const float4*)(ft + ((size_t)b*NPTS + id)*FEATC);
        #pragma unroll
        for(int j=0;j<16;j++){
            float4 v = fr[j];
            Xs[(3+4*j+0)*GX_STRIDE + tid] = tf32r(v.x);
            Xs[(3+4*j+1)*GX_STRIDE + tid] = tf32r(v.y);
            Xs[(3+4*j+2)*GX_STRIDE + tid] = tf32r(v.z);
            Xs[(3+4*j+3)*GX_STRIDE + tid] = tf32r(v.w);
        }
        #pragma unroll
        for(int k=CIN0;k<GX_ROWS;k++) Xs[k*GX_STRIDE + tid] = 0.f;
    }

    float acc[4][4][4];
    #pragma unroll
    for(int mt=0;mt<4;mt++)
        #pragma unroll
        for(int nt=0;nt<4;nt++)
            #pragma unroll
            for(int i=0;i<4;i++) acc[mt][nt][i]=0.f;
    __syncthreads();

    for(int kc=0; kc<5; kc++){
        int kb = kc*16;
        #pragma unroll
        for(int i=0;i<4;i++){
            int ix = tid + i*256;
            int o = ix >> 4, k = ix & 15;
            Wc[o*20 + k] = (kb + k < CIN0) ? tf32r(W[(size_t)o*CIN0 + kb + k]) : 0.f;
        }
        __syncthreads();
        #pragma unroll
        for(int s8=0; s8<2; s8++){
            int ko = kb + s8*8, kl = s8*8;
            float a[4][4], b[4][2];
            #pragma unroll
            for(int mt=0;mt<4;mt++){
                int r0 = (mt*16 + g)*20 + kl + tg;
                a[mt][0] = Wc[r0];
                a[mt][1] = Wc[r0 + 160];
                a[mt][2] = Wc[r0 + 4];
                a[mt][3] = Wc[r0 + 164];
            }
            #pragma unroll
            for(int nt=0;nt<4;nt++){
                int cb = wn*32 + nt*8 + g;
                b[nt][0] = Xs[(ko+tg)*GX_STRIDE + cb];
                b[nt][1] = Xs[(ko+tg+4)*GX_STRIDE + cb];
            }
            #pragma unroll
            for(int mt=0;mt<4;mt++)
                #pragma unroll
                for(int nt=0;nt<4;nt++)
                    mma8(acc[mt][nt], a[mt], b[nt]);
        }
        __syncthreads();
    }

    // ---- epilogue: stats + store ----
    float s8v[8], q8v[8];
    #pragma unroll
    for(int i=0;i<8;i++){ s8v[i]=0.f; q8v[i]=0.f; }
    #pragma unroll
    for(int mt=0;mt<4;mt++)
        #pragma unroll
        for(int nt=0;nt<4;nt++){
            float c0=acc[mt][nt][0], c1=acc[mt][nt][1];
            float c2=acc[mt][nt][2], c3=acc[mt][nt][3];
            s8v[mt*2+0] += c0+c1; q8v[mt*2+0] += c0*c0 + c1*c1;
            s8v[mt*2+1] += c2+c3; q8v[mt*2+1] += c2*c2 + c3*c3;
        }
    #pragma unroll
    for(int i=0;i<8;i++){
        s8v[i] += __shfl_xor_sync(0xffffffffu, s8v[i], 1);
        s8v[i] += __shfl_xor_sync(0xffffffffu, s8v[i], 2);
        q8v[i] += __shfl_xor_sync(0xffffffffu, q8v[i], 1);
        q8v[i] += __shfl_xor_sync(0xffffffffu, q8v[i], 2);
    }
    if(tg == 0){
        #pragma unroll
        for(int mt=0;mt<4;mt++){
            atomicAdd(&ssum[mt*16 + g],     s8v[mt*2+0]);
            atomicAdd(&ssq [mt*16 + g],     q8v[mt*2+0]);
            atomicAdd(&ssum[mt*16 + g + 8], s8v[mt*2+1]);
            atomicAdd(&ssq [mt*16 + g + 8], q8v[mt*2+1]);
        }
    }
    #pragma unroll
    for(int mt=0;mt<4;mt++)
        #pragma unroll
        for(int nt=0;nt<4;nt++){
            int m = m0 + wn*32 + nt*8 + 2*tg;
            int r0 = mt*16 + g;
            *(float2*)(Y + (size_t)r0*M + m)     = make_float2(acc[mt][nt][0], acc[mt][nt][1]);
            *(float2*)(Y + (size_t)(r0+8)*M + m) = make_float2(acc[mt][nt][2], acc[mt][nt][3]);
        }
    __syncthreads();
    if(tid < 64){
        atomicAdd(&gsum[tid], ssum[tid]);
        atomicAdd(&gsq [tid], ssq [tid]);
    }
}

// ==================================================================
// Middle-layer tensor-core GEMM (writes full Y + stats).
// ==================================================================
__global__ __launch_bounds__(256) void gemm_tc_kernel(const float* __restrict__ W,
        const float* __restrict__ X, float* __restrict__ Y,
        int Cin, int Cout, int M,
        const float* __restrict__ tsc, const float* __restrict__ tsh,
        float* __restrict__ gsum, float* __restrict__ gsq){
    __shared__ float Xs[16*264];
    __shared__ float Wc[64*20];
    __shared__ float ssum[64], ssq[64];
    int tid = threadIdx.x;
    int lane = tid & 31, wn = tid >> 5;
    int g = lane >> 2, tg = lane & 3;
    int ob = blockIdx.x * 64;
    int m0 = blockIdx.y * 256;
    if(tid < 64){ ssum[tid]=0.f; ssq[tid]=0.f; }

    float acc[4][4][4];
    #pragma unroll
    for(int mt=0;mt<4;mt++)
        #pragma unroll
        for(int nt=0;nt<4;nt++)
            #pragma unroll
            for(int i=0;i<4;i++) acc[mt][nt][i]=0.f;

    int kchunks = (Cin + 15) >> 4;
    for(int kc=0; kc<kchunks; kc++){
        int kb = kc*16;
        {
            int rr = tid >> 4, cb = (tid & 15)*16;
            int cin = kb + rr;
            float v[16];
            if(cin < Cin){
                const float4* p = (const float4*)(X + (size_t)cin*M + m0 + cb);
                #pragma unroll
                for(int j=0;j<4;j++){
                    float4 q = p[j];
                    v[4*j+0]=q.x; v[4*j+1]=q.y; v[4*j+2]=q.z; v[4*j+3]=q.w;
                }
                float s_ = tsc[cin], h_ = tsh[cin];
                #pragma unroll
                for(int j=0;j<16;j++) v[j] = tf32r(fmaxf(0.f, fmaf(s_, v[j], h_)));
            } else {
                #pragma unroll
                for(int j=0;j<16;j++) v[j]=0.f;
            }
            #pragma unroll
            for(int j=0;j<16;j++) Xs[rr*264 + cb + j] = v[j];
        }
        #pragma unroll
        for(int i=0;i<4;i++){
            int ix = tid + i*256;
            int o = ix >> 4, k = ix & 15;
            float wv = (kb + k < Cin) ? W[(size_t)(ob+o)*Cin + kb + k] : 0.f;
            Wc[o*20 + k] = tf32r(wv);
        }
        __syncthreads();
        #pragma unroll
        for(int s8=0; s8<2; s8++){
            int ko = s8*8;
            float a[4][4], b[4][2];
            #pragma unroll
            for(int mt=0;mt<4;mt++){
                int r0 = (mt*16 + g)*20 + ko + tg;
                a[mt][0] = Wc[r0];
                a[mt][1] = Wc[r0 + 160];
                a[mt][2] = Wc[r0 + 4];
                a[mt][3] = Wc[r0 + 164];
            }
            #pragma unroll
            for(int nt=0;nt<4;nt++){
                int cb = wn*32 + nt*8 + g;
                b[nt][0] = Xs[(ko+tg)*264 + cb];
                b[nt][1] = Xs[(ko+tg+4)*264 + cb];
            }
            #pragma unroll
            for(int mt=0;mt<4;mt++)
                #pragma unroll
                for(int nt=0;nt<4;nt++)
                    mma8(acc[mt][nt], a[mt], b[nt]);
        }
        __syncthreads();
    }

    float s8v[8], q8v[8];
    #pragma unroll
    for(int i=0;i<8;i++){ s8v[i]=0.f; q8v[i]=0.f; }
    #pragma unroll
    for(int mt=0;mt<4;mt++)
        #pragma unroll
        for(int nt=0;nt<4;nt++){
            float c0=acc[mt][nt][0], c1=acc[mt][nt][1];
            float c2=acc[mt][nt][2], c3=acc[mt][nt][3];
            s8v[mt*2+0] += c0+c1; q8v[mt*2+0] += c0*c0 + c1*c1;
            s8v[mt*2+1] += c2+c3; q8v[mt*2+1] += c2*c2 + c3*c3;
        }
    #pragma unroll
    for(int i=0;i<8;i++){
        s8v[i] += __shfl_xor_sync(0xffffffffu, s8v[i], 1);
        s8v[i] += __shfl_xor_sync(0xffffffffu, s8v[i], 2);
        q8v[i] += __shfl_xor_sync(0xffffffffu, q8v[i], 1);
        q8v[i] += __shfl_xor_sync(0xffffffffu, q8v[i], 2);
    }
    if(tg == 0){
        #pragma unroll
        for(int mt=0;mt<4;mt++){
            atomicAdd(&ssum[mt*16 + g],     s8v[mt*2+0]);
            atomicAdd(&ssq [mt*16 + g],     q8v[mt*2+0]);
            atomicAdd(&ssum[mt*16 + g + 8], s8v[mt*2+1]);
            atomicAdd(&ssq [mt*16 + g + 8], q8v[mt*2+1]);
        }
    }
    #pragma unroll
    for(int mt=0;mt<4;mt++)
        #pragma unroll
        for(int nt=0;nt<4;nt++){
            int m = m0 + wn*32 + nt*8 + 2*tg;
            int r0 = ob + mt*16 + g;
            *(float2*)(Y + (size_t)r0*M + m)     = make_float2(acc[mt][nt][0], acc[mt][nt][1]);
            *(float2*)(Y + (size_t)(r0+8)*M + m) = make_float2(acc[mt][nt][2], acc[mt][nt][3]);
        }
    __syncthreads();
    if(tid < 64){
        atomicAdd(&gsum[ob + tid], ssum[tid]);
        atomicAdd(&gsq [ob + tid], ssq [tid]);
    }
}

// ==================================================================
// Last-layer GEMM: no Y store. Computes stats + per-window raw max/min
// (window = ns consecutive m). Pooled arrays are [Cout][NWIN].
// ==================================================================
__global__ __launch_bounds__(256) void gemm_tc_pool_kernel(const float* __restrict__ W,
        const float* __restrict__ X, int Cin, int Cout, int M, int ns,
        const float* __restrict__ tsc, const float* __restrict__ tsh,
        float* __restrict__ gsum, float* __restrict__ gsq,
        float* __restrict__ gpmax, float* __restrict__ gpmin){
    __shared__ float Xs[16*264];
    __shared__ float Wc[64*20];
    __shared__ float ssum[64], ssq[64];
    __shared__ float pmaxS[64][8], pminS[64][8];
    int tid = threadIdx.x;
    int lane = tid & 31, wn = tid >> 5;
    int g = lane >> 2, tg = lane & 3;
    int ob = blockIdx.x * 64;
    int m0 = blockIdx.y * 256;
    if(tid < 64){ ssum[tid]=0.f; ssq[tid]=0.f; }

    float acc[4][4][4];
    #pragma unroll
    for(int mt=0;mt<4;mt++)
        #pragma unroll
        for(int nt=0;nt<4;nt++)
            #pragma unroll
            for(int i=0;i<4;i++) acc[mt][nt][i]=0.f;

    int kchunks = (Cin + 15) >> 4;
    for(int kc=0; kc<kchunks; kc++){
        int kb = kc*16;
        {
            int rr = tid >> 4, cb = (tid & 15)*16;
            int cin = kb + rr;
            float v[16];
            if(cin < Cin){
                const float4* p = (const float4*)(X + (size_t)cin*M + m0 + cb);
                #pragma unroll
                for(int j=0;j<4;j++){
                    float4 q = p[j];
                    v[4*j+0]=q.x; v[4*j+1]=q.y; v[4*j+2]=q.z; v[4*j+3]=q.w;
                }
                float s_ = tsc[cin], h_ = tsh[cin];
                #pragma unroll
                for(int j=0;j<16;j++) v[j] = tf32r(fmaxf(0.f, fmaf(s_, v[j], h_)));
            } else {
                #pragma unroll
                for(int j=0;j<16;j++) v[j]=0.f;
            }
            #pragma unroll
            for(int j=0;j<16;j++) Xs[rr*264 + cb + j] = v[j];
        }
        #pragma unroll
        for(int i=0;i<4;i++){
            int ix = tid + i*256;
            int o = ix >> 4, k = ix & 15;
            float wv = (kb + k < Cin) ? W[(size_t)(ob+o)*Cin + kb + k] : 0.f;
            Wc[o*20 + k] = tf32r(wv);
        }
        __syncthreads();
        #pragma unroll
        for(int s8=0; s8<2; s8++){
            int ko = s8*8;
            float a[4][4], b[4][2];
            #pragma unroll
            for(int mt=0;mt<4;mt++){
                int r0 = (mt*16 + g)*20 + ko + tg;
                a[mt][0] = Wc[r0];
                a[mt][1] = Wc[r0 + 160];
                a[mt][2] = Wc[r0 + 4];
                a[mt][3] = Wc[r0 + 164];
            }
            #pragma unroll
            for(int nt=0;nt<4;nt++){
                int cb = wn*32 + nt*8 + g;
                b[nt][0] = Xs[(ko+tg)*264 + cb];
                b[nt][1] = Xs[(ko+tg+4)*264 + cb];
            }
            #pragma unroll
            for(int mt=0;mt<4;mt++)
                #pragma unroll
                for(int nt=0;nt<4;nt++)
                    mma8(acc[mt][nt], a[mt], b[nt]);
        }
        __syncthreads();
    }

    // ---- stats ----
    float s8v[8], q8v[8];
    #pragma unroll
    for(int i=0;i<8;i++){ s8v[i]=0.f; q8v[i]=0.f; }
    #pragma unroll
    for(int mt=0;mt<4;mt++)
        #pragma unroll
        for(int nt=0;nt<4;nt++){
            float c0=acc[mt][nt][0], c1=acc[mt][nt][1];
            float c2=acc[mt][nt][2], c3=acc[mt][nt][3];
            s8v[mt*2+0] += c0+c1; q8v[mt*2+0] += c0*c0 + c1*c1;
            s8v[mt*2+1] += c2+c3; q8v[mt*2+1] += c2*c2 + c3*c3;
        }
    #pragma unroll
    for(int i=0;i<8;i++){
        s8v[i] += __shfl_xor_sync(0xffffffffu, s8v[i], 1);
        s8v[i] += __shfl_xor_sync(0xffffffffu, s8v[i], 2);
        q8v[i] += __shfl_xor_sync(0xffffffffu, q8v[i], 1);
        q8v[i] += __shfl_xor_sync(0xffffffffu, q8v[i], 2);
    }
    if(tg == 0){
        #pragma unroll
        for(int mt=0;mt<4;mt++){
            atomicAdd(&ssum[mt*16 + g],     s8v[mt*2+0]);
            atomicAdd(&ssq [mt*16 + g],     q8v[mt*2+0]);
            atomicAdd(&ssum[mt*16 + g + 8], s8v[mt*2+1]);
            atomicAdd(&ssq [mt*16 + g + 8], q8v[mt*2+1]);
        }
    }

    // ---- per-warp 32-column raw max/min per row ----
    #pragma unroll
    for(int mt=0;mt<4;mt++){
        float mxA=-3.4e38f, mnA=3.4e38f, mxB=-3.4e38f, mnB=3.4e38f;
        #pragma unroll
        for(int nt=0;nt<4;nt++){
            mxA = fmaxf(mxA, fmaxf(acc[mt][nt][0], acc[mt][nt][1]));
            mnA = fminf(mnA, fminf(acc[mt][nt][0], acc[mt][nt][1]));
            mxB = fmaxf(mxB, fmaxf(acc[mt][nt][2], acc[mt][nt][3]));
            mnB = fminf(mnB, fminf(acc[mt][nt][2], acc[mt][nt][3]));
        }
        #pragma unroll
        for(int o=1;o<=2;o<<=1){
            mxA = fmaxf(mxA, __shfl_xor_sync(0xffffffffu, mxA, o));
            mnA = fminf(mnA, __shfl_xor_sync(0xffffffffu, mnA, o));
            mxB = fmaxf(mxB, __shfl_xor_sync(0xffffffffu, mxB, o));
            mnB = fminf(mnB, __shfl_xor_sync(0xffffffffu, mnB, o));
        }
        if(tg == 0){
            pmaxS[mt*16 + g][wn] = mxA;   pminS[mt*16 + g][wn] = mnA;
            pmaxS[mt*16 + g + 8][wn] = mxB; pminS[mt*16 + g + 8][wn] = mnB;
        }
    }
    __syncthreads();
    // ---- combine warps into windows, write pooled ----
    int nwin = 256/ns;          // 8 (ns=32) or 4 (ns=64)
    int gsz  = ns/32;           // warps per window
    for(int i=tid; i<64*nwin; i+=256){
        int row = i / nwin, win = i % nwin;
        float mx=-3.4e38f, mn=3.4e38f;
        for(int j=0;j<gsz;j++){
            mx = fmaxf(mx, pmaxS[row][win*gsz + j]);
            mn = fminf(mn, pminS[row][win*gsz + j]);
        }
        size_t o = (size_t)(ob + row)*NWIN + m0/ns + win;
        gpmax[o] = mx; gpmin[o] = mn;
    }
    if(tid < 64){
        atomicAdd(&gsum[ob + tid], ssum[tid]);
        atomicAdd(&gsq [ob + tid], ssq [tid]);
    }
}

// ---------------- finalize BN params ----------------
__global__ void finalize_kernel(const float* __restrict__ gsum, const float* __restrict__ gsq,
                                const float* __restrict__ g, const float* __restrict__ bb,
                                float* __restrict__ sc, float* __restrict__ sh,
                                int Cout, double invM){
    int o = blockIdx.x*blockDim.x + threadIdx.x;
    if(o < Cout){
        double mean = (double)gsum[o]*invM;
        double var  = (double)gsq[o]*invM - mean*mean;
        float s = (float)((double)g[o] / sqrt(var + 1e-5));
        sc[o] = s;
        sh[o] = fmaf(-(float)mean, s, bb[o]);
    }
}

// ---------------- epilogue: BN+ReLU on pooled values ----------------
// max_k relu(s*y_k+h) == relu(s*max_k y_k + h) for s>=0 (monotone fma/relu);
// uses the window min when s<0.
__global__ void bn_pool_out_kernel(const float* __restrict__ gpmax,
                                   const float* __restrict__ gpmin,
                                   const float* __restrict__ sc, const float* __restrict__ sh,
                                   float* __restrict__ out, int Cout, int coff){
    int i = blockIdx.x*blockDim.x + threadIdx.x;
    if(i >= Cout*NWIN) return;
    int win = i & (NWIN-1);
    int co  = i >> 13;
    int s = win & 1023, b = win >> 10;
    float s_ = sc[co], h_ = sh[co];
    float v = (s_ >= 0.f) ? gpmax[(size_t)co*NWIN + win] : gpmin[(size_t)co*NWIN + win];
    out[((size_t)(b*384 + coff + co))*SPTS + s] = fmaxf(0.f, fmaf(s_, v, h_));
}

// ---------------- launch ----------------
extern "C" void kernel_launch(void* const* d_in, const int* in_sizes, int n_in,
                              void* d_out, int out_size){
    const float* xyz  = (const float*)d_in[0];
    const float* feat = (const float*)d_in[1];
    const float *w[6], *g[6], *bb[6];
    for(int L=0; L<6; L++){
        w[L]  = (const float*)d_in[2 + L*3];
        g[L]  = (const float*)d_in[3 + L*3];
        bb[L] = (const float*)d_in[4 + L*3];
    }
    float* out = (float*)d_out;
    float* newxyz  = out;                         // (8,1024,3)
    float* outfeat = out + (size_t)BATCH*SPTS*3;  // (8,384,1024)

    void *pA,*pB,*pFT,*pM,*pI0,*pI1,*pSum,*pSq,*pSc,*pSh,*pPM,*pPN;
    cudaGetSymbolAddress(&pA,  d_bufA);
    cudaGetSymbolAddress(&pB,  d_bufB);
    cudaGetSymbolAddress(&pFT, d_featT);
    cudaGetSymbolAddress(&pM,  d_meanv);
    cudaGetSymbolAddress(&pI0, d_idx0);
    cudaGetSymbolAddress(&pI1, d_idx1);
    cudaGetSymbolAddress(&pSum,d_gsum);
    cudaGetSymbolAddress(&pSq, d_gsq);
    cudaGetSymbolAddress(&pSc, d_scl);
    cudaGetSymbolAddress(&pSh, d_shf);
    cudaGetSymbolAddress(&pPM, d_pmax);
    cudaGetSymbolAddress(&pPN, d_pmin);
    float* A  = (float*)pA;  float* Bf = (float*)pB;
    float* ft = (float*)pFT; float* mv = (float*)pM;
    int* i0 = (int*)pI0; int* i1 = (int*)pI1;
    float* gsum = (float*)pSum; float* gsq = (float*)pSq;
    float* scv = (float*)pSc; float* shv = (float*)pSh;
    float* pmax = (float*)pPM; float* pmin = (float*)pPN;

    static int attr_set = 0;
    const int FPS_SMEM = 3*N1*sizeof(float);
    if(!attr_set){
        cudaFuncSetAttribute(fps_kernel, cudaFuncAttributeMaxDynamicSharedMemorySize, FPS_SMEM);
        cudaFuncSetAttribute(gemm_g_kernel, cudaFuncAttributeMaxDynamicSharedMemorySize, G_SMEM);
        attr_set = 1;
    }

    zero_stats_kernel<<<6,256>>>(gsum, gsq);
    mean_kernel<<<BATCH,256>>>(xyz, mv);
    fps_kernel<<<BATCH,1024,FPS_SMEM>>>(xyz, mv, newxyz);
    transpose_kernel<<<dim3(NPTS/32, FEATC/32, BATCH), dim3(32,8)>>>(feat, ft);
    ballq_kernel<<<(BATCH*SPTS)/8, 256>>>(xyz, newxyz, i0, i1);

    // ---- branch 0 (r=0.4, ns=32): 67 -> 64 -> 64 -> 128 ----
    gemm_g_kernel<<<dim3(1, M0/256),256,G_SMEM>>>(w[0], xyz, ft, newxyz, i0, A, M0, NS0, gsum+0*256, gsq+0*256);
    finalize_kernel<<<1,256>>>(gsum+0*256, gsq+0*256, g[0], bb[0], scv+0*256, shv+0*256, 64, 1.0/M0);
    gemm_tc_kernel<<<dim3(1, M0/256),256>>>(w[1], A, Bf, 64, 64, M0, scv+0*256, shv+0*256, gsum+1*256, gsq+1*256);
    finalize_kernel<<<1,256>>>(gsum+1*256, gsq+1*256, g[1], bb[1], scv+1*256, shv+1*256, 64, 1.0/M0);
    gemm_tc_pool_kernel<<<dim3(2, M0/256),256>>>(w[2], Bf, 64, 128, M0, NS0, scv+1*256, shv+1*256, gsum+2*256, gsq+2*256, pmax, pmin);
    finalize_kernel<<<1,256>>>(gsum+2*256, gsq+2*256, g[2], bb[2], scv+2*256, shv+2*256, 128, 1.0/M0);
    bn_pool_out_kernel<<<(128*NWIN)/256,256>>>(pmax, pmin, scv+2*256, shv+2*256, outfeat, 128, 0);

    // ---- branch 1 (r=0.8, ns=64): 67 -> 64 -> 128 -> 256 ----
    gemm_g_kernel<<<dim3(1, M1/256),256,G_SMEM>>>(w[3], xyz, ft, newxyz, i1, A, M1, NS1, gsum+3*256, gsq+3*256);
    finalize_kernel<<<1,256>>>(gsum+3*256, gsq+3*256, g[3], bb[3], scv+3*256, shv+3*256, 64, 1.0/M1);
    gemm_tc_kernel<<<dim3(2, M1/256),256>>>(w[4], A, Bf, 64, 128, M1, scv+3*256, shv+3*256, gsum+4*256, gsq+4*256);
    finalize_kernel<<<1,256>>>(gsum+4*256, gsq+4*256, g[4], bb[4], scv+4*256, shv+4*256, 128, 1.0/M1);
    gemm_tc_pool_kernel<<<dim3(4, M1/256),256>>>(w[5], Bf, 128, 256, M1, NS1, scv+4*256, shv+4*256, gsum+5*256, gsq+5*256, pmax, pmin);
    finalize_kernel<<<1,256>>>(gsum+5*256, gsq+5*256, g[5], bb[5], scv+5*256, shv+5*256, 256, 1.0/M1);
    bn_pool_out_kernel<<<(256*NWIN)/256,256>>>(pmax, pmin, scv+5*256, shv+5*256, outfeat, 256, 128);
}